// round 5
// baseline (speedup 1.0000x reference)
#include <cuda_runtime.h>
#include <cuda_bf16.h>
#include <math.h>
#include <stdint.h>

// Problem constants (fixed by the dataset)
constexpr int cN   = 20000;
constexpr int cE   = 320000;
constexpr int cIN  = 512;
constexpr int cHID = 128;
constexpr int cH   = 8;
constexpr int cC   = 64;
constexpr int cHH  = cH * cHID;   // 1024

// ---------------------------------------------------------------------------
// Scratch (static __device__ globals; no allocation allowed)
// ---------------------------------------------------------------------------
__device__ __align__(128) float         g_ft[(size_t)cN * cHH];   // GEMM out fp32
__device__ __align__(128) __nv_bfloat16 g_Ahi[(size_t)cN * cHH];  // A hi split
__device__ __align__(128) __nv_bfloat16 g_Alo[(size_t)cN * cHH];  // A lo split
__device__ __align__(128) __nv_bfloat16 g_Bhi[cHH * cHH];         // W hi, [Nout][K]
__device__ __align__(128) __nv_bfloat16 g_Blo[cHH * cHH];
__device__ float g_a1[cN * cH];
__device__ float g_a2[cN * cH];
__device__ int   g_cnt[cN];
__device__ int   g_rowptr[cN + 1];
__device__ int   g_cursor[cN];
__device__ int   g_srcsorted[cE];

// ---------------------------------------------------------------------------
// PTX helpers (base sm_80+ ISA only — NO tcgen05, the harness lowers to sm_103)
// ---------------------------------------------------------------------------
__device__ __forceinline__ uint32_t smem_u32(const void* p) {
    uint32_t a;
    asm("{ .reg .u64 t; cvta.to.shared.u64 t, %1; cvt.u32.u64 %0, t; }" : "=r"(a) : "l"(p));
    return a;
}
__device__ __forceinline__ void cp16(uint32_t dst, const void* src, bool ok) {
    int sz = ok ? 16 : 0;
    asm volatile("cp.async.cg.shared.global [%0], [%1], 16, %2;"
                 :: "r"(dst), "l"(src), "r"(sz) : "memory");
}
__device__ __forceinline__ void cp_commit() {
    asm volatile("cp.async.commit_group;" ::: "memory");
}
__device__ __forceinline__ void mma_bf16(float* d, const uint32_t* a, const uint32_t* b) {
    asm volatile(
        "mma.sync.aligned.m16n8k16.row.col.f32.bf16.bf16.f32 "
        "{%0,%1,%2,%3}, {%4,%5,%6,%7}, {%8,%9}, {%0,%1,%2,%3};"
        : "+f"(d[0]), "+f"(d[1]), "+f"(d[2]), "+f"(d[3])
        : "r"(a[0]), "r"(a[1]), "r"(a[2]), "r"(a[3]), "r"(b[0]), "r"(b[1]));
}

// ---------------------------------------------------------------------------
// CSR build
// ---------------------------------------------------------------------------
__global__ void zero_int_kernel(int* p, int n) {
    int i = blockIdx.x * blockDim.x + threadIdx.x;
    if (i < n) p[i] = 0;
}
__global__ void hist_kernel(const int* __restrict__ dst, int* __restrict__ cnt, int e) {
    int i = blockIdx.x * blockDim.x + threadIdx.x;
    if (i < e) atomicAdd(&cnt[dst[i]], 1);
}
__global__ void scan_kernel(const int* __restrict__ cnt, int* __restrict__ rowptr,
                            int* __restrict__ cursor, int n) {
    __shared__ int sh[1024];
    int tid = threadIdx.x;
    const int CH = (n + 1023) / 1024;
    int st = tid * CH;
    int s = 0;
    for (int i = 0; i < CH; i++) {
        int idx = st + i;
        if (idx < n) s += cnt[idx];
    }
    sh[tid] = s;
    __syncthreads();
    for (int d = 1; d < 1024; d <<= 1) {
        int v = (tid >= d) ? sh[tid - d] : 0;
        __syncthreads();
        sh[tid] += v;
        __syncthreads();
    }
    int run = sh[tid] - s;
    for (int i = 0; i < CH; i++) {
        int idx = st + i;
        if (idx < n) {
            rowptr[idx] = run;
            cursor[idx] = run;
            run += cnt[idx];
        }
    }
    if (tid == 1023) rowptr[n] = sh[1023];
}
__global__ void scatter_kernel(const int* __restrict__ src, const int* __restrict__ dst,
                               int* __restrict__ cursor, int* __restrict__ out, int e) {
    int i = blockIdx.x * blockDim.x + threadIdx.x;
    if (i < e) {
        int d = dst[i];
        int pos = atomicAdd(&cursor[d], 1);
        out[pos] = src[i];
    }
}

// ---------------------------------------------------------------------------
// fp32 -> bf16 hi/lo split (first-layer features)
// ---------------------------------------------------------------------------
__global__ void split_kernel(const float* __restrict__ in,
                             __nv_bfloat16* __restrict__ hi,
                             __nv_bfloat16* __restrict__ lo, int n) {
    int i = blockIdx.x * blockDim.x + threadIdx.x;
    if (i < n) {
        float v = in[i];
        __nv_bfloat16 h = __float2bfloat16(v);
        hi[i] = h;
        lo[i] = __float2bfloat16(v - __bfloat162float(h));
    }
}

// Weight prep: head-blocked W [heads][K][HIDo] -> B [Nout][K] K-major, split
__global__ void wprep_kernel(const float* __restrict__ W,
                             __nv_bfloat16* __restrict__ Bhi,
                             __nv_bfloat16* __restrict__ Blo,
                             int K, int HIDo, int total) {
    int idx = blockIdx.x * blockDim.x + threadIdx.x;
    if (idx >= total) return;
    int n = idx / K;
    int k = idx - n * K;
    int h = n / HIDo;
    int j = n - h * HIDo;
    float w = W[(size_t)h * K * HIDo + (size_t)k * HIDo + j];
    __nv_bfloat16 hi = __float2bfloat16(w);
    Bhi[idx] = hi;
    Blo[idx] = __float2bfloat16(w - __bfloat162float(hi));
}

// ---------------------------------------------------------------------------
// Split-bf16 warp-MMA GEMM with fused bias.
//   C(fp32)[M,Nout] = A(fp32) @ W(fp32)^T  via  Ahi*Bhi + Alo*Bhi + Ahi*Blo
// A: [M,K] bf16 K-major.  B: [Nout,K] bf16 K-major.
// Tile: BM=128 x BN x BK=32, 8 warps (2x4), warp tile 64 x BN/4.
// SMEM rows padded to 80B (conflict-free for the m16n8k16 fragment pattern).
// ---------------------------------------------------------------------------
template<int BN>
__global__ __launch_bounds__(256)
void gemm_mma_kernel(const __nv_bfloat16* __restrict__ Ahi,
                     const __nv_bfloat16* __restrict__ Alo,
                     const __nv_bfloat16* __restrict__ Bhi,
                     const __nv_bfloat16* __restrict__ Blo,
                     const float* __restrict__ bias,
                     float* __restrict__ C,
                     int M, int K, int ldc) {
    constexpr int MT  = 4;          // m16 tiles per warp (64 rows)
    constexpr int WNC = BN / 4;     // cols per warp
    constexpr int NTL = WNC / 8;    // n8 tiles per warp
    constexpr int ASZ = 128 * 80;   // bytes, one A operand tile (padded rows)
    constexpr int BSZ = BN * 80;
    constexpr int STAGE = 2 * ASZ + 2 * BSZ;

    extern __shared__ char smem[];
    const uint32_t sbase = smem_u32(smem);

    const int tid = threadIdx.x;
    const int wid = tid >> 5;
    const int lid = tid & 31;
    const int wr = wid >> 2;        // 0..1
    const int wc = wid & 3;         // 0..3
    const int g  = lid >> 2;
    const int t  = lid & 3;

    const int row0 = blockIdx.x * 128;
    const int col0 = blockIdx.y * BN;

    float acc[MT][NTL][4];
#pragma unroll
    for (int m = 0; m < MT; m++)
#pragma unroll
        for (int n = 0; n < NTL; n++)
#pragma unroll
            for (int q = 0; q < 4; q++) acc[m][n][q] = 0.f;

    const int nch = K >> 5;

    auto ld_stage = [&](int s, int k0) {
        const uint32_t sb = sbase + s * STAGE;
        // A: 128 rows x 4 16B chunks, hi+lo
#pragma unroll
        for (int c = tid; c < 512; c += 256) {
            int r = c >> 2, q = c & 3;
            int gr = row0 + r;
            bool ok = gr < M;
            size_t goff = (size_t)(ok ? gr : row0) * K + k0 + q * 8;
            cp16(sb + r * 80 + q * 16, Ahi + goff, ok);
            cp16(sb + ASZ + r * 80 + q * 16, Alo + goff, ok);
        }
        // B: BN rows x 4 chunks, hi+lo (always in-bounds)
#pragma unroll
        for (int c = tid; c < BN * 4; c += 256) {
            int r = c >> 2, q = c & 3;
            size_t goff = (size_t)(col0 + r) * K + k0 + q * 8;
            cp16(sb + 2 * ASZ + r * 80 + q * 16, Bhi + goff, true);
            cp16(sb + 2 * ASZ + BSZ + r * 80 + q * 16, Blo + goff, true);
        }
    };

    ld_stage(0, 0);
    cp_commit();

    for (int i = 0; i < nch; i++) {
        if (i + 1 < nch) {
            ld_stage((i + 1) & 1, (i + 1) * 32);
            cp_commit();
            asm volatile("cp.async.wait_group 1;" ::: "memory");
        } else {
            asm volatile("cp.async.wait_group 0;" ::: "memory");
        }
        __syncthreads();

        const char* sA_hi = smem + (i & 1) * STAGE;
        const char* sA_lo = sA_hi + ASZ;
        const char* sB_hi = sA_lo + ASZ;
        const char* sB_lo = sB_hi + BSZ;

#pragma unroll
        for (int ks = 0; ks < 2; ks++) {
            const int kb = ks * 32 + t * 4;   // byte offset within padded row

            uint32_t bh[NTL][2], bl[NTL][2];
#pragma unroll
            for (int n = 0; n < NTL; n++) {
                int off = (wc * WNC + n * 8 + g) * 80 + kb;
                bh[n][0] = *(const uint32_t*)(sB_hi + off);
                bh[n][1] = *(const uint32_t*)(sB_hi + off + 16);
                bl[n][0] = *(const uint32_t*)(sB_lo + off);
                bl[n][1] = *(const uint32_t*)(sB_lo + off + 16);
            }
#pragma unroll
            for (int m = 0; m < MT; m++) {
                int off = (wr * 64 + m * 16 + g) * 80 + kb;
                uint32_t ah[4], al[4];
                ah[0] = *(const uint32_t*)(sA_hi + off);
                ah[1] = *(const uint32_t*)(sA_hi + off + 640);
                ah[2] = *(const uint32_t*)(sA_hi + off + 16);
                ah[3] = *(const uint32_t*)(sA_hi + off + 656);
                al[0] = *(const uint32_t*)(sA_lo + off);
                al[1] = *(const uint32_t*)(sA_lo + off + 640);
                al[2] = *(const uint32_t*)(sA_lo + off + 16);
                al[3] = *(const uint32_t*)(sA_lo + off + 656);
#pragma unroll
                for (int n = 0; n < NTL; n++) {
                    mma_bf16(acc[m][n], ah, bh[n]);
                    mma_bf16(acc[m][n], al, bh[n]);
                    mma_bf16(acc[m][n], ah, bl[n]);
                }
            }
        }
        __syncthreads();
    }

    // Epilogue: add bias, store fp32
#pragma unroll
    for (int m = 0; m < MT; m++) {
        int r0r = row0 + wr * 64 + m * 16 + g;
        int r1r = r0r + 8;
#pragma unroll
        for (int n = 0; n < NTL; n++) {
            int cc = col0 + wc * WNC + n * 8 + t * 2;
            float bx = bias[cc], by = bias[cc + 1];
            if (r0r < M) {
                float2 v = make_float2(acc[m][n][0] + bx, acc[m][n][1] + by);
                *(float2*)(C + (size_t)r0r * ldc + cc) = v;
            }
            if (r1r < M) {
                float2 v = make_float2(acc[m][n][2] + bx, acc[m][n][3] + by);
                *(float2*)(C + (size_t)r1r * ldc + cc) = v;
            }
        }
    }
}

// ---------------------------------------------------------------------------
// Per-node attention logits (one warp per (node, head))
// ---------------------------------------------------------------------------
__global__ void logits_kernel(const float* __restrict__ ft,
                              const float* __restrict__ al, const float* __restrict__ alb,
                              const float* __restrict__ ar, const float* __restrict__ arb,
                              float* __restrict__ a1, float* __restrict__ a2,
                              int Nn, int Hn, int HIDo, int ld) {
    int gw   = (blockIdx.x * blockDim.x + threadIdx.x) >> 5;
    int lane = threadIdx.x & 31;
    if (gw >= Nn * Hn) return;
    int n = gw / Hn;
    int h = gw - n * Hn;
    const float* fp = ft + (size_t)n * ld + h * HIDo;
    float s1 = 0.f, s2 = 0.f;
    for (int j = lane; j < HIDo; j += 32) {
        float f = fp[j];
        s1 = fmaf(f, al[h * HIDo + j], s1);
        s2 = fmaf(f, ar[h * HIDo + j], s2);
    }
    for (int o = 16; o; o >>= 1) {
        s1 += __shfl_xor_sync(0xffffffffu, s1, o);
        s2 += __shfl_xor_sync(0xffffffffu, s2, o);
    }
    if (lane == 0) {
        a1[n * Hn + h] = s1 + alb[h];
        a2[n * Hn + h] = s2 + arb[h];
    }
}

// ---------------------------------------------------------------------------
// Edge-softmax + aggregation + ELU.  One warp per (node, head).
// SPLIT: write bf16 hi/lo (feeds next GEMM); else fp32 out.
// ---------------------------------------------------------------------------
template<int NR, bool SPLIT>
__global__ void aggregate_kernel(const float* __restrict__ ft,
                                 const float* __restrict__ a1,
                                 const float* __restrict__ a2,
                                 const int* __restrict__ rowptr,
                                 const int* __restrict__ srcs,
                                 float* __restrict__ out,
                                 __nv_bfloat16* __restrict__ outHi,
                                 __nv_bfloat16* __restrict__ outLo,
                                 int Nn, int Hn, int ld) {
    constexpr int HIDo = NR * 32;
    int gw   = (blockIdx.x * blockDim.x + threadIdx.x) >> 5;
    int lane = threadIdx.x & 31;
    if (gw >= Nn * Hn) return;
    int n = gw / Hn;
    int h = gw - n * Hn;
    int beg = rowptr[n];
    int end = rowptr[n + 1];
    float a1n = a1[n * Hn + h];

    float m = -1e30f;
    for (int e = beg + lane; e < end; e += 32) {
        float s = a1n + a2[srcs[e] * Hn + h];
        s = (s >= 0.f) ? s : 0.01f * s;
        m = fmaxf(m, s);
    }
    for (int o = 16; o; o >>= 1) m = fmaxf(m, __shfl_xor_sync(0xffffffffu, m, o));

    float den = 0.f;
    for (int e = beg + lane; e < end; e += 32) {
        float s = a1n + a2[srcs[e] * Hn + h];
        s = (s >= 0.f) ? s : 0.01f * s;
        den += __expf(s - m);
    }
    for (int o = 16; o; o >>= 1) den += __shfl_xor_sync(0xffffffffu, den, o);
    float inv = 1.f / den;

    float acc[NR];
#pragma unroll
    for (int r = 0; r < NR; r++) acc[r] = 0.f;
    const float* fbase = ft + h * HIDo + lane;

    for (int e0 = beg; e0 < end; e0 += 32) {
        int e = e0 + lane;
        float w = 0.f;
        int sv = 0;
        if (e < end) {
            sv = srcs[e];
            float s = a1n + a2[sv * Hn + h];
            s = (s >= 0.f) ? s : 0.01f * s;
            w = __expf(s - m) * inv;
        }
        int cnt = min(32, end - e0);
        for (int i = 0; i < cnt; i++) {
            float wi = __shfl_sync(0xffffffffu, w, i);
            int   si = __shfl_sync(0xffffffffu, sv, i);
            const float* fp = fbase + (size_t)si * ld;
#pragma unroll
            for (int r = 0; r < NR; r++) acc[r] = fmaf(wi, fp[r * 32], acc[r]);
        }
    }

    size_t obase = (size_t)n * ld + h * HIDo + lane;
#pragma unroll
    for (int r = 0; r < NR; r++) {
        float v = acc[r];
        v = (v > 0.f) ? v : expm1f(v);
        if (SPLIT) {
            __nv_bfloat16 hi = __float2bfloat16(v);
            outHi[obase + r * 32] = hi;
            outLo[obase + r * 32] = __float2bfloat16(v - __bfloat162float(hi));
        } else {
            out[obase + r * 32] = v;
        }
    }
}

// ---------------------------------------------------------------------------
// Host launch
// ---------------------------------------------------------------------------
extern "C" void kernel_launch(void* const* d_in, const int* in_sizes, int n_in,
                              void* d_out, int out_size) {
    const float* features = (const float*)d_in[0];
    const int*   src      = (const int*)d_in[1];
    const int*   dst      = (const int*)d_in[2];
    const float* W0  = (const float*)d_in[3];
    const float* b0  = (const float*)d_in[4];
    const float* al0 = (const float*)d_in[5];
    const float* alb0= (const float*)d_in[6];
    const float* ar0 = (const float*)d_in[7];
    const float* arb0= (const float*)d_in[8];
    const float* W1  = (const float*)d_in[9];
    const float* b1  = (const float*)d_in[10];
    const float* al1 = (const float*)d_in[11];
    const float* alb1= (const float*)d_in[12];
    const float* ar1 = (const float*)d_in[13];
    const float* arb1= (const float*)d_in[14];
    const float* Wf  = (const float*)d_in[15];
    const float* bfv = (const float*)d_in[16];
    const float* alf = (const float*)d_in[17];
    const float* albf= (const float*)d_in[18];
    const float* arf = (const float*)d_in[19];
    const float* arbf= (const float*)d_in[20];

    float *ft, *a1, *a2;
    __nv_bfloat16 *Ahi, *Alo, *Bhi, *Blo;
    int *cnt, *rowptr, *cursor, *ssrc;
    cudaGetSymbolAddress((void**)&ft,  g_ft);
    cudaGetSymbolAddress((void**)&Ahi, g_Ahi);
    cudaGetSymbolAddress((void**)&Alo, g_Alo);
    cudaGetSymbolAddress((void**)&Bhi, g_Bhi);
    cudaGetSymbolAddress((void**)&Blo, g_Blo);
    cudaGetSymbolAddress((void**)&a1, g_a1);
    cudaGetSymbolAddress((void**)&a2, g_a2);
    cudaGetSymbolAddress((void**)&cnt, g_cnt);
    cudaGetSymbolAddress((void**)&rowptr, g_rowptr);
    cudaGetSymbolAddress((void**)&cursor, g_cursor);
    cudaGetSymbolAddress((void**)&ssrc, g_srcsorted);

    // SMEM: 2 stages * (2*A(128*80) + 2*B(BN*80))
    constexpr int SMEM128 = 2 * (2 * 128 * 80 + 2 * 128 * 80);  // 81920
    constexpr int SMEM64  = 2 * (2 * 128 * 80 + 2 * 64 * 80);   // 61440
    cudaFuncSetAttribute(gemm_mma_kernel<128>,
                         cudaFuncAttributeMaxDynamicSharedMemorySize, SMEM128);
    cudaFuncSetAttribute(gemm_mma_kernel<64>,
                         cudaFuncAttributeMaxDynamicSharedMemorySize, SMEM64);

    // --- CSR build ---
    zero_int_kernel<<<(cN + 255) / 256, 256>>>(cnt, cN);
    hist_kernel<<<(cE + 255) / 256, 256>>>(dst, cnt, cE);
    scan_kernel<<<1, 1024>>>(cnt, rowptr, cursor, cN);
    scatter_kernel<<<(cE + 255) / 256, 256>>>(src, dst, cursor, ssrc, cE);

    const int gridM = (cN + 127) / 128;   // 157
    const int warpBlocksH = (cN * cH * 32 + 255) / 256;
    const int warpBlocks1 = (cN * 32 + 255) / 256;

    // --- layer 0 ---
    split_kernel<<<(cN * cIN + 255) / 256, 256>>>(features, Ahi, Alo, cN * cIN);
    wprep_kernel<<<(cHH * cIN + 255) / 256, 256>>>(W0, Bhi, Blo, cIN, cHID, cHH * cIN);
    gemm_mma_kernel<128><<<dim3(gridM, 8), 256, SMEM128>>>(Ahi, Alo, Bhi, Blo, b0, ft,
                                                           cN, cIN, cHH);
    logits_kernel<<<warpBlocksH, 256>>>(ft, al0, alb0, ar0, arb0, a1, a2, cN, cH, cHID, cHH);
    aggregate_kernel<4, true><<<warpBlocksH, 256>>>(ft, a1, a2, rowptr, ssrc,
                                                    nullptr, Ahi, Alo, cN, cH, cHH);

    // --- layer 1 ---
    wprep_kernel<<<(cHH * cHH + 255) / 256, 256>>>(W1, Bhi, Blo, cHH, cHID, cHH * cHH);
    gemm_mma_kernel<128><<<dim3(gridM, 8), 256, SMEM128>>>(Ahi, Alo, Bhi, Blo, b1, ft,
                                                           cN, cHH, cHH);
    logits_kernel<<<warpBlocksH, 256>>>(ft, al1, alb1, ar1, arb1, a1, a2, cN, cH, cHID, cHH);
    aggregate_kernel<4, true><<<warpBlocksH, 256>>>(ft, a1, a2, rowptr, ssrc,
                                                    nullptr, Ahi, Alo, cN, cH, cHH);

    // --- final layer ---
    wprep_kernel<<<(cC * cHH + 255) / 256, 256>>>(Wf, Bhi, Blo, cHH, cC, cC * cHH);
    gemm_mma_kernel<64><<<dim3(gridM, 1), 256, SMEM64>>>(Ahi, Alo, Bhi, Blo, bfv, ft,
                                                         cN, cHH, cC);
    logits_kernel<<<warpBlocks1, 256>>>(ft, alf, albf, arf, arbf, a1, a2, cN, 1, cC, cC);
    aggregate_kernel<2, false><<<warpBlocks1, 256>>>(ft, a1, a2, rowptr, ssrc,
                                                     (float*)d_out, nullptr, nullptr,
                                                     cN, 1, cC);
}

// round 6
// speedup vs baseline: 1.1762x; 1.1762x over previous
#include <cuda_runtime.h>
#include <cuda_bf16.h>
#include <math.h>
#include <stdint.h>

// Problem constants (fixed by the dataset)
constexpr int cN   = 20000;
constexpr int cE   = 320000;
constexpr int cIN  = 512;
constexpr int cHID = 128;
constexpr int cH   = 8;
constexpr int cC   = 64;
constexpr int cHH  = cH * cHID;   // 1024

// ---------------------------------------------------------------------------
// Scratch (static __device__ globals; no allocation allowed)
// ---------------------------------------------------------------------------
__device__ __align__(128) float         g_ft[(size_t)cN * cHH];   // GEMM out fp32
__device__ __align__(128) __nv_bfloat16 g_Ahi[(size_t)cN * cHH];  // A hi split
__device__ __align__(128) __nv_bfloat16 g_Alo[(size_t)cN * cHH];  // A lo split
__device__ __align__(128) __nv_bfloat16 g_Bhi[cHH * cHH];         // W hi, [Nout][K]
__device__ __align__(128) __nv_bfloat16 g_Blo[cHH * cHH];
__device__ float g_a1[cN * cH];
__device__ float g_a2[cN * cH];
__device__ int   g_cnt[cN];
__device__ int   g_rowptr[cN + 1];
__device__ int   g_cursor[cN];
__device__ int   g_srcsorted[cE];

// ---------------------------------------------------------------------------
// PTX helpers (base sm_80+ ISA only — harness lowers to plain sm_103)
// ---------------------------------------------------------------------------
__device__ __forceinline__ uint32_t smem_u32(const void* p) {
    uint32_t a;
    asm("{ .reg .u64 t; cvta.to.shared.u64 t, %1; cvt.u32.u64 %0, t; }" : "=r"(a) : "l"(p));
    return a;
}
__device__ __forceinline__ void cp16(uint32_t dst, const void* src, bool ok) {
    int sz = ok ? 16 : 0;
    asm volatile("cp.async.cg.shared.global [%0], [%1], 16, %2;"
                 :: "r"(dst), "l"(src), "r"(sz) : "memory");
}
__device__ __forceinline__ void cp_commit() {
    asm volatile("cp.async.commit_group;" ::: "memory");
}
__device__ __forceinline__ void mma_bf16(float* d, const uint32_t* a, const uint32_t* b) {
    asm volatile(
        "mma.sync.aligned.m16n8k16.row.col.f32.bf16.bf16.f32 "
        "{%0,%1,%2,%3}, {%4,%5,%6,%7}, {%8,%9}, {%0,%1,%2,%3};"
        : "+f"(d[0]), "+f"(d[1]), "+f"(d[2]), "+f"(d[3])
        : "r"(a[0]), "r"(a[1]), "r"(a[2]), "r"(a[3]), "r"(b[0]), "r"(b[1]));
}

// ---------------------------------------------------------------------------
// CSR build
// ---------------------------------------------------------------------------
__global__ void zero_int_kernel(int* p, int n) {
    int i = blockIdx.x * blockDim.x + threadIdx.x;
    if (i < n) p[i] = 0;
}
__global__ void hist_kernel(const int* __restrict__ dst, int* __restrict__ cnt, int e) {
    int i = blockIdx.x * blockDim.x + threadIdx.x;
    if (i < e) atomicAdd(&cnt[dst[i]], 1);
}
__global__ void scan_kernel(const int* __restrict__ cnt, int* __restrict__ rowptr,
                            int* __restrict__ cursor, int n) {
    __shared__ int sh[1024];
    int tid = threadIdx.x;
    const int CH = (n + 1023) / 1024;
    int st = tid * CH;
    int s = 0;
    for (int i = 0; i < CH; i++) {
        int idx = st + i;
        if (idx < n) s += cnt[idx];
    }
    sh[tid] = s;
    __syncthreads();
    for (int d = 1; d < 1024; d <<= 1) {
        int v = (tid >= d) ? sh[tid - d] : 0;
        __syncthreads();
        sh[tid] += v;
        __syncthreads();
    }
    int run = sh[tid] - s;
    for (int i = 0; i < CH; i++) {
        int idx = st + i;
        if (idx < n) {
            rowptr[idx] = run;
            cursor[idx] = run;
            run += cnt[idx];
        }
    }
    if (tid == 1023) rowptr[n] = sh[1023];
}
__global__ void scatter_kernel(const int* __restrict__ src, const int* __restrict__ dst,
                               int* __restrict__ cursor, int* __restrict__ out, int e) {
    int i = blockIdx.x * blockDim.x + threadIdx.x;
    if (i < e) {
        int d = dst[i];
        int pos = atomicAdd(&cursor[d], 1);
        out[pos] = src[i];
    }
}

// ---------------------------------------------------------------------------
// fp32 -> bf16 hi/lo split (first-layer features), float4 vectorized
// ---------------------------------------------------------------------------
__global__ void split_kernel(const float* __restrict__ in,
                             __nv_bfloat16* __restrict__ hi,
                             __nv_bfloat16* __restrict__ lo, int n4) {
    int i = blockIdx.x * blockDim.x + threadIdx.x;
    if (i >= n4) return;
    float4 v = ((const float4*)in)[i];
    __nv_bfloat162 hA = __floats2bfloat162_rn(v.x, v.y);
    __nv_bfloat162 hB = __floats2bfloat162_rn(v.z, v.w);
    __nv_bfloat162 lA = __floats2bfloat162_rn(v.x - __bfloat162float(hA.x),
                                              v.y - __bfloat162float(hA.y));
    __nv_bfloat162 lB = __floats2bfloat162_rn(v.z - __bfloat162float(hB.x),
                                              v.w - __bfloat162float(hB.y));
    ((__nv_bfloat162*)hi)[i * 2]     = hA;
    ((__nv_bfloat162*)hi)[i * 2 + 1] = hB;
    ((__nv_bfloat162*)lo)[i * 2]     = lA;
    ((__nv_bfloat162*)lo)[i * 2 + 1] = lB;
}

// Weight prep: head-blocked W [heads][K][HIDo] -> B [Nout][K] K-major, split
__global__ void wprep_kernel(const float* __restrict__ W,
                             __nv_bfloat16* __restrict__ Bhi,
                             __nv_bfloat16* __restrict__ Blo,
                             int K, int HIDo, int total) {
    int idx = blockIdx.x * blockDim.x + threadIdx.x;
    if (idx >= total) return;
    int n = idx / K;
    int k = idx - n * K;
    int h = n / HIDo;
    int j = n - h * HIDo;
    float w = W[(size_t)h * K * HIDo + (size_t)k * HIDo + j];
    __nv_bfloat16 hi = __float2bfloat16(w);
    Bhi[idx] = hi;
    Blo[idx] = __float2bfloat16(w - __bfloat162float(hi));
}

// ---------------------------------------------------------------------------
// Split-bf16 warp-MMA GEMM with fused bias.
//   C(fp32)[M,Nout] = A(fp32) @ W(fp32)^T  via  Ahi*Bhi + Alo*Bhi + Ahi*Blo
// Tile: BM=128 x BN x BK=32, 8 warps (2x4), warp tile 64 x BN/4.
// grid = (colBlocks, rowBlocks): col varies fastest so concurrent CTAs share
// the same A row panel in L2.
// __launch_bounds__(256,2): cap regs at 128 -> 2 CTAs/SM, overlap LDS & HMMA.
// ---------------------------------------------------------------------------
template<int BN>
__global__ __launch_bounds__(256, 2)
void gemm_mma_kernel(const __nv_bfloat16* __restrict__ Ahi,
                     const __nv_bfloat16* __restrict__ Alo,
                     const __nv_bfloat16* __restrict__ Bhi,
                     const __nv_bfloat16* __restrict__ Blo,
                     const float* __restrict__ bias,
                     float* __restrict__ C,
                     int M, int K, int ldc) {
    constexpr int MT  = 4;          // m16 tiles per warp (64 rows)
    constexpr int WNC = BN / 4;     // cols per warp
    constexpr int NTL = WNC / 8;    // n8 tiles per warp
    constexpr int ASZ = 128 * 80;   // bytes, one A operand tile (padded rows)
    constexpr int BSZ = BN * 80;
    constexpr int STAGE = 2 * ASZ + 2 * BSZ;

    extern __shared__ char smem[];
    const uint32_t sbase = smem_u32(smem);

    const int tid = threadIdx.x;
    const int wid = tid >> 5;
    const int lid = tid & 31;
    const int wr = wid >> 2;        // 0..1
    const int wc = wid & 3;         // 0..3
    const int g  = lid >> 2;
    const int t  = lid & 3;

    const int row0 = blockIdx.y * 128;
    const int col0 = blockIdx.x * BN;

    float acc[MT][NTL][4];
#pragma unroll
    for (int m = 0; m < MT; m++)
#pragma unroll
        for (int n = 0; n < NTL; n++)
#pragma unroll
            for (int q = 0; q < 4; q++) acc[m][n][q] = 0.f;

    const int nch = K >> 5;

    auto ld_stage = [&](int s, int k0) {
        const uint32_t sb = sbase + s * STAGE;
#pragma unroll
        for (int c = tid; c < 512; c += 256) {
            int r = c >> 2, q = c & 3;
            int gr = row0 + r;
            bool ok = gr < M;
            size_t goff = (size_t)(ok ? gr : row0) * K + k0 + q * 8;
            cp16(sb + r * 80 + q * 16, Ahi + goff, ok);
            cp16(sb + ASZ + r * 80 + q * 16, Alo + goff, ok);
        }
#pragma unroll
        for (int c = tid; c < BN * 4; c += 256) {
            int r = c >> 2, q = c & 3;
            size_t goff = (size_t)(col0 + r) * K + k0 + q * 8;
            cp16(sb + 2 * ASZ + r * 80 + q * 16, Bhi + goff, true);
            cp16(sb + 2 * ASZ + BSZ + r * 80 + q * 16, Blo + goff, true);
        }
    };

    ld_stage(0, 0);
    cp_commit();

    for (int i = 0; i < nch; i++) {
        if (i + 1 < nch) {
            ld_stage((i + 1) & 1, (i + 1) * 32);
            cp_commit();
            asm volatile("cp.async.wait_group 1;" ::: "memory");
        } else {
            asm volatile("cp.async.wait_group 0;" ::: "memory");
        }
        __syncthreads();

        const char* sA_hi = smem + (i & 1) * STAGE;
        const char* sA_lo = sA_hi + ASZ;
        const char* sB_hi = sA_lo + ASZ;
        const char* sB_lo = sB_hi + BSZ;

#pragma unroll
        for (int ks = 0; ks < 2; ks++) {
            const int kb = ks * 32 + t * 4;   // byte offset within padded row

            uint32_t bh[NTL][2], bl[NTL][2];
#pragma unroll
            for (int n = 0; n < NTL; n++) {
                int off = (wc * WNC + n * 8 + g) * 80 + kb;
                bh[n][0] = *(const uint32_t*)(sB_hi + off);
                bh[n][1] = *(const uint32_t*)(sB_hi + off + 16);
                bl[n][0] = *(const uint32_t*)(sB_lo + off);
                bl[n][1] = *(const uint32_t*)(sB_lo + off + 16);
            }
#pragma unroll
            for (int m = 0; m < MT; m++) {
                int off = (wr * 64 + m * 16 + g) * 80 + kb;
                uint32_t ah[4], al[4];
                ah[0] = *(const uint32_t*)(sA_hi + off);
                ah[1] = *(const uint32_t*)(sA_hi + off + 640);
                ah[2] = *(const uint32_t*)(sA_hi + off + 16);
                ah[3] = *(const uint32_t*)(sA_hi + off + 656);
                al[0] = *(const uint32_t*)(sA_lo + off);
                al[1] = *(const uint32_t*)(sA_lo + off + 640);
                al[2] = *(const uint32_t*)(sA_lo + off + 16);
                al[3] = *(const uint32_t*)(sA_lo + off + 656);
#pragma unroll
                for (int n = 0; n < NTL; n++) {
                    mma_bf16(acc[m][n], ah, bh[n]);
                    mma_bf16(acc[m][n], al, bh[n]);
                    mma_bf16(acc[m][n], ah, bl[n]);
                }
            }
        }
        __syncthreads();
    }

    // Epilogue: add bias, store fp32
#pragma unroll
    for (int m = 0; m < MT; m++) {
        int r0r = row0 + wr * 64 + m * 16 + g;
        int r1r = r0r + 8;
#pragma unroll
        for (int n = 0; n < NTL; n++) {
            int cc = col0 + wc * WNC + n * 8 + t * 2;
            float bx = bias[cc], by = bias[cc + 1];
            if (r0r < M) {
                float2 v = make_float2(acc[m][n][0] + bx, acc[m][n][1] + by);
                *(float2*)(C + (size_t)r0r * ldc + cc) = v;
            }
            if (r1r < M) {
                float2 v = make_float2(acc[m][n][2] + bx, acc[m][n][3] + by);
                *(float2*)(C + (size_t)r1r * ldc + cc) = v;
            }
        }
    }
}

// ---------------------------------------------------------------------------
// Per-node attention logits (one warp per (node, head))
// ---------------------------------------------------------------------------
__global__ void logits_kernel(const float* __restrict__ ft,
                              const float* __restrict__ al, const float* __restrict__ alb,
                              const float* __restrict__ ar, const float* __restrict__ arb,
                              float* __restrict__ a1, float* __restrict__ a2,
                              int Nn, int Hn, int HIDo, int ld) {
    int gw   = (blockIdx.x * blockDim.x + threadIdx.x) >> 5;
    int lane = threadIdx.x & 31;
    if (gw >= Nn * Hn) return;
    int n = gw / Hn;
    int h = gw - n * Hn;
    const float* fp = ft + (size_t)n * ld + h * HIDo;
    float s1 = 0.f, s2 = 0.f;
    for (int j = lane; j < HIDo; j += 32) {
        float f = fp[j];
        s1 = fmaf(f, al[h * HIDo + j], s1);
        s2 = fmaf(f, ar[h * HIDo + j], s2);
    }
    for (int o = 16; o; o >>= 1) {
        s1 += __shfl_xor_sync(0xffffffffu, s1, o);
        s2 += __shfl_xor_sync(0xffffffffu, s2, o);
    }
    if (lane == 0) {
        a1[n * Hn + h] = s1 + alb[h];
        a2[n * Hn + h] = s2 + arb[h];
    }
}

// ---------------------------------------------------------------------------
// Edge-softmax + aggregation + ELU.  One warp per (node, head).
// Two passes: (1) segment max, (2) fused denom + unnormalized weighted gather,
// scaled by 1/den at the end (mathematically identical to normalize-then-sum).
// VEC floats per lane (VEC*32 == head dim). Gather = one LDG.128/LDG.64 per
// lane per edge (fully coalesced).
// SPLIT: write bf16 hi/lo (feeds next GEMM); else fp32 out.
// ---------------------------------------------------------------------------
template<int VEC, bool SPLIT>
__global__ void aggregate_kernel(const float* __restrict__ ft,
                                 const float* __restrict__ a1,
                                 const float* __restrict__ a2,
                                 const int* __restrict__ rowptr,
                                 const int* __restrict__ srcs,
                                 float* __restrict__ out,
                                 __nv_bfloat16* __restrict__ outHi,
                                 __nv_bfloat16* __restrict__ outLo,
                                 int Nn, int Hn, int ld) {
    constexpr int HIDo = VEC * 32;
    int gw   = (blockIdx.x * blockDim.x + threadIdx.x) >> 5;
    int lane = threadIdx.x & 31;
    if (gw >= Nn * Hn) return;
    int n = gw / Hn;
    int h = gw - n * Hn;
    int beg = rowptr[n];
    int end = rowptr[n + 1];
    float a1n = a1[n * Hn + h];

    // pass 1: segment max of leaky-relu logits
    float m = -1e30f;
    for (int e = beg + lane; e < end; e += 32) {
        float s = a1n + a2[srcs[e] * Hn + h];
        s = (s >= 0.f) ? s : 0.01f * s;
        m = fmaxf(m, s);
    }
    for (int o = 16; o; o >>= 1) m = fmaxf(m, __shfl_xor_sync(0xffffffffu, m, o));

    // pass 2: fused denom + unnormalized weighted feature accumulation
    float acc[VEC];
#pragma unroll
    for (int r = 0; r < VEC; r++) acc[r] = 0.f;
    float den = 0.f;
    const float* fbase = ft + h * HIDo;

    for (int e0 = beg; e0 < end; e0 += 32) {
        int e = e0 + lane;
        float ev = 0.f;
        int sv = 0;
        if (e < end) {
            sv = srcs[e];
            float s = a1n + a2[sv * Hn + h];
            s = (s >= 0.f) ? s : 0.01f * s;
            ev = __expf(s - m);
        }
        den += ev;
        int cnt = min(32, end - e0);
        for (int i = 0; i < cnt; i++) {
            float wi = __shfl_sync(0xffffffffu, ev, i);
            int   si = __shfl_sync(0xffffffffu, sv, i);
            const float* fp = fbase + (size_t)si * ld;
            if (VEC == 4) {
                float4 v = *((const float4*)fp + lane);
                acc[0] = fmaf(wi, v.x, acc[0]);
                acc[1] = fmaf(wi, v.y, acc[1]);
                acc[2] = fmaf(wi, v.z, acc[2]);
                acc[3] = fmaf(wi, v.w, acc[3]);
            } else {
                float2 v = *((const float2*)fp + lane);
                acc[0] = fmaf(wi, v.x, acc[0]);
                acc[1] = fmaf(wi, v.y, acc[1]);
            }
        }
    }
    for (int o = 16; o; o >>= 1) den += __shfl_xor_sync(0xffffffffu, den, o);
    float inv = 1.f / den;

    float r[VEC];
#pragma unroll
    for (int q = 0; q < VEC; q++) {
        float v = acc[q] * inv;
        r[q] = (v > 0.f) ? v : expm1f(v);
    }

    size_t ob = (size_t)n * ld + h * HIDo + lane * VEC;
    if (SPLIT) {
        if (VEC == 4) {
            __nv_bfloat162 hA = __floats2bfloat162_rn(r[0], r[1]);
            __nv_bfloat162 hB = __floats2bfloat162_rn(r[2], r[3]);
            __nv_bfloat162 lA = __floats2bfloat162_rn(r[0] - __bfloat162float(hA.x),
                                                      r[1] - __bfloat162float(hA.y));
            __nv_bfloat162 lB = __floats2bfloat162_rn(r[2] - __bfloat162float(hB.x),
                                                      r[3] - __bfloat162float(hB.y));
            *(__nv_bfloat162*)(outHi + ob)     = hA;
            *(__nv_bfloat162*)(outHi + ob + 2) = hB;
            *(__nv_bfloat162*)(outLo + ob)     = lA;
            *(__nv_bfloat162*)(outLo + ob + 2) = lB;
        } else {
            __nv_bfloat162 hA = __floats2bfloat162_rn(r[0], r[1]);
            __nv_bfloat162 lA = __floats2bfloat162_rn(r[0] - __bfloat162float(hA.x),
                                                      r[1] - __bfloat162float(hA.y));
            *(__nv_bfloat162*)(outHi + ob) = hA;
            *(__nv_bfloat162*)(outLo + ob) = lA;
        }
    } else {
        if (VEC == 4) {
            *(float4*)(out + ob) = make_float4(r[0], r[1], r[2], r[3]);
        } else {
            *(float2*)(out + ob) = make_float2(r[0], r[1]);
        }
    }
}

// ---------------------------------------------------------------------------
// Host launch
// ---------------------------------------------------------------------------
extern "C" void kernel_launch(void* const* d_in, const int* in_sizes, int n_in,
                              void* d_out, int out_size) {
    const float* features = (const float*)d_in[0];
    const int*   src      = (const int*)d_in[1];
    const int*   dst      = (const int*)d_in[2];
    const float* W0  = (const float*)d_in[3];
    const float* b0  = (const float*)d_in[4];
    const float* al0 = (const float*)d_in[5];
    const float* alb0= (const float*)d_in[6];
    const float* ar0 = (const float*)d_in[7];
    const float* arb0= (const float*)d_in[8];
    const float* W1  = (const float*)d_in[9];
    const float* b1  = (const float*)d_in[10];
    const float* al1 = (const float*)d_in[11];
    const float* alb1= (const float*)d_in[12];
    const float* ar1 = (const float*)d_in[13];
    const float* arb1= (const float*)d_in[14];
    const float* Wf  = (const float*)d_in[15];
    const float* bfv = (const float*)d_in[16];
    const float* alf = (const float*)d_in[17];
    const float* albf= (const float*)d_in[18];
    const float* arf = (const float*)d_in[19];
    const float* arbf= (const float*)d_in[20];

    float *ft, *a1, *a2;
    __nv_bfloat16 *Ahi, *Alo, *Bhi, *Blo;
    int *cnt, *rowptr, *cursor, *ssrc;
    cudaGetSymbolAddress((void**)&ft,  g_ft);
    cudaGetSymbolAddress((void**)&Ahi, g_Ahi);
    cudaGetSymbolAddress((void**)&Alo, g_Alo);
    cudaGetSymbolAddress((void**)&Bhi, g_Bhi);
    cudaGetSymbolAddress((void**)&Blo, g_Blo);
    cudaGetSymbolAddress((void**)&a1, g_a1);
    cudaGetSymbolAddress((void**)&a2, g_a2);
    cudaGetSymbolAddress((void**)&cnt, g_cnt);
    cudaGetSymbolAddress((void**)&rowptr, g_rowptr);
    cudaGetSymbolAddress((void**)&cursor, g_cursor);
    cudaGetSymbolAddress((void**)&ssrc, g_srcsorted);

    // SMEM: 2 stages * (2*A(128*80) + 2*B(BN*80))
    constexpr int SMEM128 = 2 * (2 * 128 * 80 + 2 * 128 * 80);  // 81920
    constexpr int SMEM64  = 2 * (2 * 128 * 80 + 2 * 64 * 80);   // 61440
    cudaFuncSetAttribute(gemm_mma_kernel<128>,
                         cudaFuncAttributeMaxDynamicSharedMemorySize, SMEM128);
    cudaFuncSetAttribute(gemm_mma_kernel<64>,
                         cudaFuncAttributeMaxDynamicSharedMemorySize, SMEM64);

    // --- CSR build ---
    zero_int_kernel<<<(cN + 255) / 256, 256>>>(cnt, cN);
    hist_kernel<<<(cE + 255) / 256, 256>>>(dst, cnt, cE);
    scan_kernel<<<1, 1024>>>(cnt, rowptr, cursor, cN);
    scatter_kernel<<<(cE + 255) / 256, 256>>>(src, dst, cursor, ssrc, cE);

    const int gridM = (cN + 127) / 128;   // 157
    const int warpBlocksH = (cN * cH * 32 + 255) / 256;
    const int warpBlocks1 = (cN * 32 + 255) / 256;

    // --- layer 0 ---
    split_kernel<<<(cN * cIN / 4 + 255) / 256, 256>>>(features, Ahi, Alo, cN * cIN / 4);
    wprep_kernel<<<(cHH * cIN + 255) / 256, 256>>>(W0, Bhi, Blo, cIN, cHID, cHH * cIN);
    gemm_mma_kernel<128><<<dim3(8, gridM), 256, SMEM128>>>(Ahi, Alo, Bhi, Blo, b0, ft,
                                                           cN, cIN, cHH);
    logits_kernel<<<warpBlocksH, 256>>>(ft, al0, alb0, ar0, arb0, a1, a2, cN, cH, cHID, cHH);
    aggregate_kernel<4, true><<<warpBlocksH, 256>>>(ft, a1, a2, rowptr, ssrc,
                                                    nullptr, Ahi, Alo, cN, cH, cHH);

    // --- layer 1 ---
    wprep_kernel<<<(cHH * cHH + 255) / 256, 256>>>(W1, Bhi, Blo, cHH, cHID, cHH * cHH);
    gemm_mma_kernel<128><<<dim3(8, gridM), 256, SMEM128>>>(Ahi, Alo, Bhi, Blo, b1, ft,
                                                           cN, cHH, cHH);
    logits_kernel<<<warpBlocksH, 256>>>(ft, al1, alb1, ar1, arb1, a1, a2, cN, cH, cHID, cHH);
    aggregate_kernel<4, true><<<warpBlocksH, 256>>>(ft, a1, a2, rowptr, ssrc,
                                                    nullptr, Ahi, Alo, cN, cH, cHH);

    // --- final layer ---
    wprep_kernel<<<(cC * cHH + 255) / 256, 256>>>(Wf, Bhi, Blo, cHH, cC, cC * cHH);
    gemm_mma_kernel<64><<<dim3(1, gridM), 256, SMEM64>>>(Ahi, Alo, Bhi, Blo, bfv, ft,
                                                         cN, cHH, cC);
    logits_kernel<<<warpBlocks1, 256>>>(ft, alf, albf, arf, arbf, a1, a2, cN, 1, cC, cC);
    aggregate_kernel<2, false><<<warpBlocks1, 256>>>(ft, a1, a2, rowptr, ssrc,
                                                     (float*)d_out, nullptr, nullptr,
                                                     cN, 1, cC);
}

// round 7
// speedup vs baseline: 1.4521x; 1.2346x over previous
#include <cuda_runtime.h>
#include <cuda_fp16.h>
#include <math.h>
#include <stdint.h>

// Problem constants (fixed by the dataset)
constexpr int cN   = 20000;
constexpr int cE   = 320000;
constexpr int cIN  = 512;
constexpr int cHID = 128;
constexpr int cH   = 8;
constexpr int cC   = 64;
constexpr int cHH  = cH * cHID;   // 1024

// ---------------------------------------------------------------------------
// Scratch (static __device__ globals; no allocation allowed)
// ---------------------------------------------------------------------------
__device__ __align__(128) float  g_ft[(size_t)cN * cHH];   // GEMM out fp32
__device__ __align__(128) __half g_Ahi[(size_t)cN * cHH];  // A hi split (fp16)
__device__ __align__(128) __half g_Alo[(size_t)cN * cHH];  // A lo split (fp16)
__device__ __align__(128) __half g_Bh[cHH * cHH];          // W fp16, [Nout][K]
__device__ float g_a1[cN * cH];
__device__ float g_a2[cN * cH];
__device__ float g_c1[cH];        // per-head logit constants (bias terms)
__device__ float g_c2[cH];
__device__ int   g_cnt[cN];
__device__ int   g_rowptr[cN + 1];
__device__ int   g_cursor[cN];
__device__ int   g_srcsorted[cE];

// ---------------------------------------------------------------------------
// PTX helpers (base sm_80+ ISA only — harness lowers to plain sm_103)
// ---------------------------------------------------------------------------
__device__ __forceinline__ uint32_t smem_u32(const void* p) {
    uint32_t a;
    asm("{ .reg .u64 t; cvta.to.shared.u64 t, %1; cvt.u32.u64 %0, t; }" : "=r"(a) : "l"(p));
    return a;
}
__device__ __forceinline__ void cp16(uint32_t dst, const void* src, bool ok) {
    int sz = ok ? 16 : 0;
    asm volatile("cp.async.cg.shared.global [%0], [%1], 16, %2;"
                 :: "r"(dst), "l"(src), "r"(sz) : "memory");
}
__device__ __forceinline__ void cp_commit() {
    asm volatile("cp.async.commit_group;" ::: "memory");
}
__device__ __forceinline__ void mma_f16(float* d, const uint32_t* a, const uint32_t* b) {
    asm volatile(
        "mma.sync.aligned.m16n8k16.row.col.f32.f16.f16.f32 "
        "{%0,%1,%2,%3}, {%4,%5,%6,%7}, {%8,%9}, {%0,%1,%2,%3};"
        : "+f"(d[0]), "+f"(d[1]), "+f"(d[2]), "+f"(d[3])
        : "r"(a[0]), "r"(a[1]), "r"(a[2]), "r"(a[3]), "r"(b[0]), "r"(b[1]));
}

// ---------------------------------------------------------------------------
// CSR build
// ---------------------------------------------------------------------------
__global__ void zero_int_kernel(int* p, int n) {
    int i = blockIdx.x * blockDim.x + threadIdx.x;
    if (i < n) p[i] = 0;
}
__global__ void hist_kernel(const int* __restrict__ dst, int* __restrict__ cnt, int e) {
    int i = blockIdx.x * blockDim.x + threadIdx.x;
    if (i < e) atomicAdd(&cnt[dst[i]], 1);
}
__global__ void scan_kernel(const int* __restrict__ cnt, int* __restrict__ rowptr,
                            int* __restrict__ cursor, int n) {
    __shared__ int sh[1024];
    int tid = threadIdx.x;
    const int CH = (n + 1023) / 1024;
    int st = tid * CH;
    int s = 0;
    for (int i = 0; i < CH; i++) {
        int idx = st + i;
        if (idx < n) s += cnt[idx];
    }
    sh[tid] = s;
    __syncthreads();
    for (int d = 1; d < 1024; d <<= 1) {
        int v = (tid >= d) ? sh[tid - d] : 0;
        __syncthreads();
        sh[tid] += v;
        __syncthreads();
    }
    int run = sh[tid] - s;
    for (int i = 0; i < CH; i++) {
        int idx = st + i;
        if (idx < n) {
            rowptr[idx] = run;
            cursor[idx] = run;
            run += cnt[idx];
        }
    }
    if (tid == 1023) rowptr[n] = sh[1023];
}
__global__ void scatter_kernel(const int* __restrict__ src, const int* __restrict__ dst,
                               int* __restrict__ cursor, int* __restrict__ out, int e) {
    int i = blockIdx.x * blockDim.x + threadIdx.x;
    if (i < e) {
        int d = dst[i];
        int pos = atomicAdd(&cursor[d], 1);
        out[pos] = src[i];
    }
}

// ---------------------------------------------------------------------------
// fp32 -> fp16 hi/lo split (first-layer features), float4 vectorized
// ---------------------------------------------------------------------------
__global__ void split_kernel(const float* __restrict__ in,
                             __half* __restrict__ hi,
                             __half* __restrict__ lo, int n4) {
    int i = blockIdx.x * blockDim.x + threadIdx.x;
    if (i >= n4) return;
    float4 v = ((const float4*)in)[i];
    __half h0 = __float2half_rn(v.x), h1 = __float2half_rn(v.y);
    __half h2 = __float2half_rn(v.z), h3 = __float2half_rn(v.w);
    __half l0 = __float2half_rn(v.x - __half2float(h0));
    __half l1 = __float2half_rn(v.y - __half2float(h1));
    __half l2 = __float2half_rn(v.z - __half2float(h2));
    __half l3 = __float2half_rn(v.w - __half2float(h3));
    ((__half2*)hi)[i * 2]     = __halves2half2(h0, h1);
    ((__half2*)hi)[i * 2 + 1] = __halves2half2(h2, h3);
    ((__half2*)lo)[i * 2]     = __halves2half2(l0, l1);
    ((__half2*)lo)[i * 2 + 1] = __halves2half2(l2, l3);
}

// Weight prep: head-blocked W [heads][K][HIDo] -> B [Nout][K] K-major, fp16
__global__ void wprep_kernel(const float* __restrict__ W,
                             __half* __restrict__ Bh,
                             int K, int HIDo, int total) {
    int idx = blockIdx.x * blockDim.x + threadIdx.x;
    if (idx >= total) return;
    int n = idx / K;
    int k = idx - n * K;
    int h = n / HIDo;
    int j = n - h * HIDo;
    float w = W[(size_t)h * K * HIDo + (size_t)k * HIDo + j];
    Bh[idx] = __float2half_rn(w);
}

// ---------------------------------------------------------------------------
// Per-head logit constants: c1[h] = alb[h] + dot(bias_head, al_head)
// One warp per head.
// ---------------------------------------------------------------------------
__global__ void logit_const_kernel(const float* __restrict__ bias,
                                   const float* __restrict__ al,
                                   const float* __restrict__ alb,
                                   const float* __restrict__ ar,
                                   const float* __restrict__ arb,
                                   float* __restrict__ c1, float* __restrict__ c2,
                                   int Hn, int HIDo) {
    int h = threadIdx.x >> 5;
    int lane = threadIdx.x & 31;
    if (h >= Hn) return;
    float s1 = 0.f, s2 = 0.f;
    for (int j = lane; j < HIDo; j += 32) {
        float b = bias[h * HIDo + j];
        s1 = fmaf(b, al[h * HIDo + j], s1);
        s2 = fmaf(b, ar[h * HIDo + j], s2);
    }
    for (int o = 16; o; o >>= 1) {
        s1 += __shfl_xor_sync(0xffffffffu, s1, o);
        s2 += __shfl_xor_sync(0xffffffffu, s2, o);
    }
    if (lane == 0) {
        c1[h] = s1 + alb[h];
        c2[h] = s2 + arb[h];
    }
}

__global__ void logit_init_kernel(const float* __restrict__ c1,
                                  const float* __restrict__ c2,
                                  float* __restrict__ a1, float* __restrict__ a2,
                                  int total, int Hn) {
    int i = blockIdx.x * blockDim.x + threadIdx.x;
    if (i >= total) return;
    int h = i % Hn;
    a1[i] = c1[h];
    a2[i] = c2[h];
}

// ---------------------------------------------------------------------------
// 2-term fp16 warp-MMA GEMM with fused bias + fused attention-logit dots.
//   C(fp32)[M,Nout] = A(fp32) @ W(fp16)^T  via  Ahi*B + Alo*B
// A: [M,K] fp16 hi/lo K-major.  B: [Nout,K] fp16 K-major.
// Tile: BM=128 x BN x BK=32, 8 warps (2x4), 3-stage cp.async pipeline.
// Epilogue: C store + per-row partial dots with al/ar -> atomicAdd a1/a2.
// BN == head dim so blockIdx.x == head.
// ---------------------------------------------------------------------------
template<int BN>
__global__ __launch_bounds__(256, 2)
void gemm_mma_kernel(const __half* __restrict__ Ahi,
                     const __half* __restrict__ Alo,
                     const __half* __restrict__ Bh,
                     const float* __restrict__ bias,
                     const float* __restrict__ al,
                     const float* __restrict__ ar,
                     float* __restrict__ a1g,
                     float* __restrict__ a2g,
                     float* __restrict__ C,
                     int M, int K, int ldc, int Hn) {
    constexpr int MT  = 4;          // m16 tiles per warp (64 rows)
    constexpr int WNC = BN / 4;     // cols per warp
    constexpr int NTL = WNC / 8;    // n8 tiles per warp
    constexpr int ASZ = 128 * 80;   // bytes, one A operand tile (padded rows)
    constexpr int BSZ = BN * 80;
    constexpr int STAGE = 2 * ASZ + BSZ;

    extern __shared__ char smem[];
    const uint32_t sbase = smem_u32(smem);

    const int tid = threadIdx.x;
    const int wid = tid >> 5;
    const int lid = tid & 31;
    const int wr = wid >> 2;        // 0..1
    const int wc = wid & 3;         // 0..3
    const int g  = lid >> 2;
    const int t  = lid & 3;

    const int row0 = blockIdx.y * 128;
    const int col0 = blockIdx.x * BN;
    const int h    = blockIdx.x;    // head index (BN == head dim)

    float acc[MT][NTL][4];
#pragma unroll
    for (int m = 0; m < MT; m++)
#pragma unroll
        for (int n = 0; n < NTL; n++)
#pragma unroll
            for (int q = 0; q < 4; q++) acc[m][n][q] = 0.f;

    const int nch = K >> 5;

    auto ld_stage = [&](int s, int k0) {
        const uint32_t sb = sbase + s * STAGE;
#pragma unroll
        for (int c = tid; c < 512; c += 256) {
            int r = c >> 2, q = c & 3;
            int gr = row0 + r;
            bool ok = gr < M;
            size_t goff = (size_t)(ok ? gr : row0) * K + k0 + q * 8;
            cp16(sb + r * 80 + q * 16, Ahi + goff, ok);
            cp16(sb + ASZ + r * 80 + q * 16, Alo + goff, ok);
        }
#pragma unroll
        for (int c = tid; c < BN * 4; c += 256) {
            int r = c >> 2, q = c & 3;
            size_t goff = (size_t)(col0 + r) * K + k0 + q * 8;
            cp16(sb + 2 * ASZ + r * 80 + q * 16, Bh + goff, true);
        }
    };

    ld_stage(0, 0);
    cp_commit();
    ld_stage(1, 32);
    cp_commit();

    for (int i = 0; i < nch; i++) {
        if (i + 2 < nch) {
            ld_stage((i + 2) % 3, (i + 2) * 32);
            cp_commit();
            asm volatile("cp.async.wait_group 2;" ::: "memory");
        } else if (i + 1 < nch) {
            asm volatile("cp.async.wait_group 1;" ::: "memory");
        } else {
            asm volatile("cp.async.wait_group 0;" ::: "memory");
        }
        __syncthreads();

        const char* sA_hi = smem + (i % 3) * STAGE;
        const char* sA_lo = sA_hi + ASZ;
        const char* sB    = sA_lo + ASZ;

#pragma unroll
        for (int ks = 0; ks < 2; ks++) {
            const int kb = ks * 32 + t * 4;   // byte offset within padded row

            uint32_t bf[NTL][2];
#pragma unroll
            for (int n = 0; n < NTL; n++) {
                int off = (wc * WNC + n * 8 + g) * 80 + kb;
                bf[n][0] = *(const uint32_t*)(sB + off);
                bf[n][1] = *(const uint32_t*)(sB + off + 16);
            }
#pragma unroll
            for (int m = 0; m < MT; m++) {
                int off = (wr * 64 + m * 16 + g) * 80 + kb;
                uint32_t ah[4], al_[4];
                ah[0] = *(const uint32_t*)(sA_hi + off);
                ah[1] = *(const uint32_t*)(sA_hi + off + 640);
                ah[2] = *(const uint32_t*)(sA_hi + off + 16);
                ah[3] = *(const uint32_t*)(sA_hi + off + 656);
                al_[0] = *(const uint32_t*)(sA_lo + off);
                al_[1] = *(const uint32_t*)(sA_lo + off + 640);
                al_[2] = *(const uint32_t*)(sA_lo + off + 16);
                al_[3] = *(const uint32_t*)(sA_lo + off + 656);
#pragma unroll
                for (int n = 0; n < NTL; n++) {
                    mma_f16(acc[m][n], ah, bf[n]);
                    mma_f16(acc[m][n], al_, bf[n]);
                }
            }
        }
        __syncthreads();
    }

    // ---- Epilogue: bias add + C store + fused logit partial dots ----
    float alv[NTL][2], arv[NTL][2], bv[NTL][2];
#pragma unroll
    for (int n = 0; n < NTL; n++) {
        int cc = col0 + wc * WNC + n * 8 + t * 2;
        alv[n][0] = al[cc]; alv[n][1] = al[cc + 1];
        arv[n][0] = ar[cc]; arv[n][1] = ar[cc + 1];
        bv[n][0]  = bias[cc]; bv[n][1] = bias[cc + 1];
    }

#pragma unroll
    for (int m = 0; m < MT; m++) {
        int r0r = row0 + wr * 64 + m * 16 + g;
        int r1r = r0r + 8;
        float p1a = 0.f, p2a = 0.f, p1b = 0.f, p2b = 0.f;
#pragma unroll
        for (int n = 0; n < NTL; n++) {
            float c0 = acc[m][n][0] + bv[n][0];
            float c1 = acc[m][n][1] + bv[n][1];
            float c2 = acc[m][n][2] + bv[n][0];
            float c3 = acc[m][n][3] + bv[n][1];
            int cc = col0 + wc * WNC + n * 8 + t * 2;
            if (r0r < M)
                *(float2*)(C + (size_t)r0r * ldc + cc) = make_float2(c0, c1);
            if (r1r < M)
                *(float2*)(C + (size_t)r1r * ldc + cc) = make_float2(c2, c3);
            p1a = fmaf(c0, alv[n][0], fmaf(c1, alv[n][1], p1a));
            p2a = fmaf(c0, arv[n][0], fmaf(c1, arv[n][1], p2a));
            p1b = fmaf(c2, alv[n][0], fmaf(c3, alv[n][1], p1b));
            p2b = fmaf(c2, arv[n][0], fmaf(c3, arv[n][1], p2b));
        }
        // reduce across the 4 lanes (t = 0..3) sharing each row
#pragma unroll
        for (int o = 1; o <= 2; o <<= 1) {
            p1a += __shfl_xor_sync(0xffffffffu, p1a, o);
            p2a += __shfl_xor_sync(0xffffffffu, p2a, o);
            p1b += __shfl_xor_sync(0xffffffffu, p1b, o);
            p2b += __shfl_xor_sync(0xffffffffu, p2b, o);
        }
        if (t == 0) {
            if (r0r < M) {
                atomicAdd(&a1g[r0r * Hn + h], p1a);
                atomicAdd(&a2g[r0r * Hn + h], p2a);
            }
            if (r1r < M) {
                atomicAdd(&a1g[r1r * Hn + h], p1b);
                atomicAdd(&a2g[r1r * Hn + h], p2b);
            }
        }
    }
}

// ---------------------------------------------------------------------------
// Edge-softmax + aggregation + ELU.  One warp per (node, head).
// Pass 1: segment max.  Pass 2: fused denom + unnormalized weighted gather.
// SPLIT: write fp16 hi/lo (feeds next GEMM); else fp32 out.
// ---------------------------------------------------------------------------
template<int VEC, bool SPLIT>
__global__ void aggregate_kernel(const float* __restrict__ ft,
                                 const float* __restrict__ a1,
                                 const float* __restrict__ a2,
                                 const int* __restrict__ rowptr,
                                 const int* __restrict__ srcs,
                                 float* __restrict__ out,
                                 __half* __restrict__ outHi,
                                 __half* __restrict__ outLo,
                                 int Nn, int Hn, int ld) {
    constexpr int HIDo = VEC * 32;
    int gw   = (blockIdx.x * blockDim.x + threadIdx.x) >> 5;
    int lane = threadIdx.x & 31;
    if (gw >= Nn * Hn) return;
    int n = gw / Hn;
    int h = gw - n * Hn;
    int beg = rowptr[n];
    int end = rowptr[n + 1];
    float a1n = a1[n * Hn + h];

    // pass 1: segment max of leaky-relu logits
    float m = -1e30f;
    for (int e = beg + lane; e < end; e += 32) {
        float s = a1n + a2[srcs[e] * Hn + h];
        s = (s >= 0.f) ? s : 0.01f * s;
        m = fmaxf(m, s);
    }
    for (int o = 16; o; o >>= 1) m = fmaxf(m, __shfl_xor_sync(0xffffffffu, m, o));

    // pass 2: fused denom + unnormalized weighted feature accumulation
    float acc[VEC];
#pragma unroll
    for (int r = 0; r < VEC; r++) acc[r] = 0.f;
    float den = 0.f;
    const float* fbase = ft + h * HIDo;

    for (int e0 = beg; e0 < end; e0 += 32) {
        int e = e0 + lane;
        float ev = 0.f;
        int sv = 0;
        if (e < end) {
            sv = srcs[e];
            float s = a1n + a2[sv * Hn + h];
            s = (s >= 0.f) ? s : 0.01f * s;
            ev = __expf(s - m);
        }
        den += ev;
        int cnt = min(32, end - e0);
        for (int i = 0; i < cnt; i++) {
            float wi = __shfl_sync(0xffffffffu, ev, i);
            int   si = __shfl_sync(0xffffffffu, sv, i);
            const float* fp = fbase + (size_t)si * ld;
            if (VEC == 4) {
                float4 v = *((const float4*)fp + lane);
                acc[0] = fmaf(wi, v.x, acc[0]);
                acc[1] = fmaf(wi, v.y, acc[1]);
                acc[2] = fmaf(wi, v.z, acc[2]);
                acc[3] = fmaf(wi, v.w, acc[3]);
            } else {
                float2 v = *((const float2*)fp + lane);
                acc[0] = fmaf(wi, v.x, acc[0]);
                acc[1] = fmaf(wi, v.y, acc[1]);
            }
        }
    }
    for (int o = 16; o; o >>= 1) den += __shfl_xor_sync(0xffffffffu, den, o);
    float inv = 1.f / den;

    float r[VEC];
#pragma unroll
    for (int q = 0; q < VEC; q++) {
        float v = acc[q] * inv;
        r[q] = (v > 0.f) ? v : expm1f(v);
    }

    size_t ob = (size_t)n * ld + h * HIDo + lane * VEC;
    if (SPLIT) {
        __half hv[VEC], lv[VEC];
#pragma unroll
        for (int q = 0; q < VEC; q++) {
            hv[q] = __float2half_rn(r[q]);
            lv[q] = __float2half_rn(r[q] - __half2float(hv[q]));
        }
        if (VEC == 4) {
            *(__half2*)(outHi + ob)     = __halves2half2(hv[0], hv[1]);
            *(__half2*)(outHi + ob + 2) = __halves2half2(hv[2], hv[3]);
            *(__half2*)(outLo + ob)     = __halves2half2(lv[0], lv[1]);
            *(__half2*)(outLo + ob + 2) = __halves2half2(lv[2], lv[3]);
        } else {
            *(__half2*)(outHi + ob) = __halves2half2(hv[0], hv[1]);
            *(__half2*)(outLo + ob) = __halves2half2(lv[0], lv[1]);
        }
    } else {
        if (VEC == 4) {
            *(float4*)(out + ob) = make_float4(r[0], r[1], r[2], r[3]);
        } else {
            *(float2*)(out + ob) = make_float2(r[0], r[1]);
        }
    }
}

// ---------------------------------------------------------------------------
// Host launch
// ---------------------------------------------------------------------------
extern "C" void kernel_launch(void* const* d_in, const int* in_sizes, int n_in,
                              void* d_out, int out_size) {
    const float* features = (const float*)d_in[0];
    const int*   src      = (const int*)d_in[1];
    const int*   dst      = (const int*)d_in[2];
    const float* W0  = (const float*)d_in[3];
    const float* b0  = (const float*)d_in[4];
    const float* al0 = (const float*)d_in[5];
    const float* alb0= (const float*)d_in[6];
    const float* ar0 = (const float*)d_in[7];
    const float* arb0= (const float*)d_in[8];
    const float* W1  = (const float*)d_in[9];
    const float* b1  = (const float*)d_in[10];
    const float* al1 = (const float*)d_in[11];
    const float* alb1= (const float*)d_in[12];
    const float* ar1 = (const float*)d_in[13];
    const float* arb1= (const float*)d_in[14];
    const float* Wf  = (const float*)d_in[15];
    const float* bfv = (const float*)d_in[16];
    const float* alf = (const float*)d_in[17];
    const float* albf= (const float*)d_in[18];
    const float* arf = (const float*)d_in[19];
    const float* arbf= (const float*)d_in[20];

    float *ft, *a1, *a2, *c1, *c2;
    __half *Ahi, *Alo, *Bh;
    int *cnt, *rowptr, *cursor, *ssrc;
    cudaGetSymbolAddress((void**)&ft,  g_ft);
    cudaGetSymbolAddress((void**)&Ahi, g_Ahi);
    cudaGetSymbolAddress((void**)&Alo, g_Alo);
    cudaGetSymbolAddress((void**)&Bh,  g_Bh);
    cudaGetSymbolAddress((void**)&a1, g_a1);
    cudaGetSymbolAddress((void**)&a2, g_a2);
    cudaGetSymbolAddress((void**)&c1, g_c1);
    cudaGetSymbolAddress((void**)&c2, g_c2);
    cudaGetSymbolAddress((void**)&cnt, g_cnt);
    cudaGetSymbolAddress((void**)&rowptr, g_rowptr);
    cudaGetSymbolAddress((void**)&cursor, g_cursor);
    cudaGetSymbolAddress((void**)&ssrc, g_srcsorted);

    // SMEM: 3 stages * (2*A(128*80) + B(BN*80))
    constexpr int SMEM128 = 3 * (2 * 128 * 80 + 128 * 80);  // 92160
    constexpr int SMEM64  = 3 * (2 * 128 * 80 + 64 * 80);   // 76800
    cudaFuncSetAttribute(gemm_mma_kernel<128>,
                         cudaFuncAttributeMaxDynamicSharedMemorySize, SMEM128);
    cudaFuncSetAttribute(gemm_mma_kernel<64>,
                         cudaFuncAttributeMaxDynamicSharedMemorySize, SMEM64);

    // --- CSR build ---
    zero_int_kernel<<<(cN + 255) / 256, 256>>>(cnt, cN);
    hist_kernel<<<(cE + 255) / 256, 256>>>(dst, cnt, cE);
    scan_kernel<<<1, 1024>>>(cnt, rowptr, cursor, cN);
    scatter_kernel<<<(cE + 255) / 256, 256>>>(src, dst, cursor, ssrc, cE);

    const int gridM = (cN + 127) / 128;   // 157
    const int warpBlocksH = (cN * cH * 32 + 255) / 256;
    const int warpBlocks1 = (cN * 32 + 255) / 256;

    // --- layer 0 ---
    split_kernel<<<(cN * cIN / 4 + 255) / 256, 256>>>(features, Ahi, Alo, cN * cIN / 4);
    wprep_kernel<<<(cHH * cIN + 255) / 256, 256>>>(W0, Bh, cIN, cHID, cHH * cIN);
    logit_const_kernel<<<1, 256>>>(b0, al0, alb0, ar0, arb0, c1, c2, cH, cHID);
    logit_init_kernel<<<(cN * cH + 255) / 256, 256>>>(c1, c2, a1, a2, cN * cH, cH);
    gemm_mma_kernel<128><<<dim3(8, gridM), 256, SMEM128>>>(
        Ahi, Alo, Bh, b0, al0, ar0, a1, a2, ft, cN, cIN, cHH, cH);
    aggregate_kernel<4, true><<<warpBlocksH, 256>>>(ft, a1, a2, rowptr, ssrc,
                                                    nullptr, Ahi, Alo, cN, cH, cHH);

    // --- layer 1 ---
    wprep_kernel<<<(cHH * cHH + 255) / 256, 256>>>(W1, Bh, cHH, cHID, cHH * cHH);
    logit_const_kernel<<<1, 256>>>(b1, al1, alb1, ar1, arb1, c1, c2, cH, cHID);
    logit_init_kernel<<<(cN * cH + 255) / 256, 256>>>(c1, c2, a1, a2, cN * cH, cH);
    gemm_mma_kernel<128><<<dim3(8, gridM), 256, SMEM128>>>(
        Ahi, Alo, Bh, b1, al1, ar1, a1, a2, ft, cN, cHH, cHH, cH);
    aggregate_kernel<4, true><<<warpBlocksH, 256>>>(ft, a1, a2, rowptr, ssrc,
                                                    nullptr, Ahi, Alo, cN, cH, cHH);

    // --- final layer ---
    wprep_kernel<<<(cC * cHH + 255) / 256, 256>>>(Wf, Bh, cHH, cC, cC * cHH);
    logit_const_kernel<<<1, 32>>>(bfv, alf, albf, arf, arbf, c1, c2, 1, cC);
    logit_init_kernel<<<(cN + 255) / 256, 256>>>(c1, c2, a1, a2, cN, 1);
    gemm_mma_kernel<64><<<dim3(1, gridM), 256, SMEM64>>>(
        Ahi, Alo, Bh, bfv, alf, arf, a1, a2, ft, cN, cHH, cC, 1);
    aggregate_kernel<2, false><<<warpBlocks1, 256>>>(ft, a1, a2, rowptr, ssrc,
                                                     (float*)d_out, nullptr, nullptr,
                                                     cN, 1, cC);
}

// round 8
// speedup vs baseline: 1.5650x; 1.0777x over previous
#include <cuda_runtime.h>
#include <cuda_fp16.h>
#include <math.h>
#include <stdint.h>

// Problem constants (fixed by the dataset)
constexpr int cN   = 20000;
constexpr int cE   = 320000;
constexpr int cIN  = 512;
constexpr int cHID = 128;
constexpr int cH   = 8;
constexpr int cC   = 64;
constexpr int cHH  = cH * cHID;   // 1024

// ---------------------------------------------------------------------------
// Scratch (static __device__ globals; no allocation allowed)
// ---------------------------------------------------------------------------
__device__ __align__(128) float  g_ft[(size_t)cN * cHH];   // GEMM out (fp32 or fp16 alias)
__device__ __align__(128) __half g_Ahi[(size_t)cN * cHH];  // A hi split (fp16)
__device__ __align__(128) __half g_Alo[(size_t)cN * cHH];  // A lo split (fp16)
__device__ __align__(128) __half g_Bh[cHH * cHH];          // W fp16, [Nout][K]
__device__ float g_a1a[cN * cH];
__device__ float g_a2a[cN * cH];
__device__ float g_a1b[cN * cH];
__device__ float g_a2b[cN * cH];
__device__ float g_c1[3 * cH];    // per-layer, per-head logit constants
__device__ float g_c2[3 * cH];
__device__ int   g_cnt[cN];
__device__ int   g_rowptr[cN + 1];
__device__ int   g_cursor[cN];
__device__ int   g_srcsorted[cE];

// ---------------------------------------------------------------------------
// PTX helpers (base sm_80+ ISA only — harness lowers to plain sm_103)
// ---------------------------------------------------------------------------
__device__ __forceinline__ uint32_t smem_u32(const void* p) {
    uint32_t a;
    asm("{ .reg .u64 t; cvta.to.shared.u64 t, %1; cvt.u32.u64 %0, t; }" : "=r"(a) : "l"(p));
    return a;
}
__device__ __forceinline__ void cp16(uint32_t dst, const void* src, bool ok) {
    int sz = ok ? 16 : 0;
    asm volatile("cp.async.cg.shared.global [%0], [%1], 16, %2;"
                 :: "r"(dst), "l"(src), "r"(sz) : "memory");
}
__device__ __forceinline__ void cp_commit() {
    asm volatile("cp.async.commit_group;" ::: "memory");
}
__device__ __forceinline__ void mma_f16(float* d, const uint32_t* a, const uint32_t* b) {
    asm volatile(
        "mma.sync.aligned.m16n8k16.row.col.f32.f16.f16.f32 "
        "{%0,%1,%2,%3}, {%4,%5,%6,%7}, {%8,%9}, {%0,%1,%2,%3};"
        : "+f"(d[0]), "+f"(d[1]), "+f"(d[2]), "+f"(d[3])
        : "r"(a[0]), "r"(a[1]), "r"(a[2]), "r"(a[3]), "r"(b[0]), "r"(b[1]));
}

// ---------------------------------------------------------------------------
// CSR build
// ---------------------------------------------------------------------------
__global__ void zero_int_kernel(int* p, int n) {
    int i = blockIdx.x * blockDim.x + threadIdx.x;
    if (i < n) p[i] = 0;
}
__global__ void hist_kernel(const int* __restrict__ dst, int* __restrict__ cnt, int e) {
    int i = blockIdx.x * blockDim.x + threadIdx.x;
    if (i < e) atomicAdd(&cnt[dst[i]], 1);
}
__global__ void scan_kernel(const int* __restrict__ cnt, int* __restrict__ rowptr,
                            int* __restrict__ cursor, int n) {
    __shared__ int sh[1024];
    int tid = threadIdx.x;
    const int CH = (n + 1023) / 1024;
    int st = tid * CH;
    int s = 0;
    for (int i = 0; i < CH; i++) {
        int idx = st + i;
        if (idx < n) s += cnt[idx];
    }
    sh[tid] = s;
    __syncthreads();
    for (int d = 1; d < 1024; d <<= 1) {
        int v = (tid >= d) ? sh[tid - d] : 0;
        __syncthreads();
        sh[tid] += v;
        __syncthreads();
    }
    int run = sh[tid] - s;
    for (int i = 0; i < CH; i++) {
        int idx = st + i;
        if (idx < n) {
            rowptr[idx] = run;
            cursor[idx] = run;
            run += cnt[idx];
        }
    }
    if (tid == 1023) rowptr[n] = sh[1023];
}
__global__ void scatter_kernel(const int* __restrict__ src, const int* __restrict__ dst,
                               int* __restrict__ cursor, int* __restrict__ out, int e) {
    int i = blockIdx.x * blockDim.x + threadIdx.x;
    if (i < e) {
        int d = dst[i];
        int pos = atomicAdd(&cursor[d], 1);
        out[pos] = src[i];
    }
}

// ---------------------------------------------------------------------------
// fp32 -> fp16 hi/lo split (first-layer features), float4 vectorized
// ---------------------------------------------------------------------------
__global__ void split_kernel(const float* __restrict__ in,
                             __half* __restrict__ hi,
                             __half* __restrict__ lo, int n4) {
    int i = blockIdx.x * blockDim.x + threadIdx.x;
    if (i >= n4) return;
    float4 v = ((const float4*)in)[i];
    __half h0 = __float2half_rn(v.x), h1 = __float2half_rn(v.y);
    __half h2 = __float2half_rn(v.z), h3 = __float2half_rn(v.w);
    __half l0 = __float2half_rn(v.x - __half2float(h0));
    __half l1 = __float2half_rn(v.y - __half2float(h1));
    __half l2 = __float2half_rn(v.z - __half2float(h2));
    __half l3 = __float2half_rn(v.w - __half2float(h3));
    ((__half2*)hi)[i * 2]     = __halves2half2(h0, h1);
    ((__half2*)hi)[i * 2 + 1] = __halves2half2(h2, h3);
    ((__half2*)lo)[i * 2]     = __halves2half2(l0, l1);
    ((__half2*)lo)[i * 2 + 1] = __halves2half2(l2, l3);
}

// Weight prep: head-blocked W [heads][K][HIDo] -> B [Nout][K] K-major, fp16
__global__ void wprep_kernel(const float* __restrict__ W,
                             __half* __restrict__ Bh,
                             int K, int HIDo, int total) {
    int idx = blockIdx.x * blockDim.x + threadIdx.x;
    if (idx >= total) return;
    int n = idx / K;
    int k = idx - n * K;
    int h = n / HIDo;
    int j = n - h * HIDo;
    float w = W[(size_t)h * K * HIDo + (size_t)k * HIDo + j];
    Bh[idx] = __float2half_rn(w);
}

// ---------------------------------------------------------------------------
// Per-head logit constants: c1[h] = alb[h] + dot(bias_head, al_head)
// ---------------------------------------------------------------------------
__global__ void logit_const_kernel(const float* __restrict__ bias,
                                   const float* __restrict__ al,
                                   const float* __restrict__ alb,
                                   const float* __restrict__ ar,
                                   const float* __restrict__ arb,
                                   float* __restrict__ c1, float* __restrict__ c2,
                                   int Hn, int HIDo) {
    int h = threadIdx.x >> 5;
    int lane = threadIdx.x & 31;
    if (h >= Hn) return;
    float s1 = 0.f, s2 = 0.f;
    for (int j = lane; j < HIDo; j += 32) {
        float b = bias[h * HIDo + j];
        s1 = fmaf(b, al[h * HIDo + j], s1);
        s2 = fmaf(b, ar[h * HIDo + j], s2);
    }
    for (int o = 16; o; o >>= 1) {
        s1 += __shfl_xor_sync(0xffffffffu, s1, o);
        s2 += __shfl_xor_sync(0xffffffffu, s2, o);
    }
    if (lane == 0) {
        c1[h] = s1 + alb[h];
        c2[h] = s2 + arb[h];
    }
}

__global__ void logit_init_kernel(const float* __restrict__ c1,
                                  const float* __restrict__ c2,
                                  float* __restrict__ a1, float* __restrict__ a2,
                                  int total, int Hn) {
    int i = blockIdx.x * blockDim.x + threadIdx.x;
    if (i >= total) return;
    int h = i % Hn;
    a1[i] = c1[h];
    a2[i] = c2[h];
}

// ---------------------------------------------------------------------------
// 2-term fp16 warp-MMA GEMM with fused bias + fused attention-logit dots.
//   C = A(fp32 as hi/lo fp16) @ W(fp16)^T,  D = Ahi*B + Alo*B (fp32 acc)
// Tile: BM=128 x BN x BK=32, 8 warps (2x4), 3-stage cp.async pipeline.
// HALFOUT: write C as fp16 (rn) — feeds the fp16-gather aggregate.
// Epilogue also computes per-row a1/a2 partial dots -> atomicAdd.
// ---------------------------------------------------------------------------
template<int BN, bool HALFOUT>
__global__ __launch_bounds__(256, 2)
void gemm_mma_kernel(const __half* __restrict__ Ahi,
                     const __half* __restrict__ Alo,
                     const __half* __restrict__ Bh,
                     const float* __restrict__ bias,
                     const float* __restrict__ al,
                     const float* __restrict__ ar,
                     float* __restrict__ a1g,
                     float* __restrict__ a2g,
                     void* __restrict__ Cv,
                     int M, int K, int ldc, int Hn) {
    constexpr int MT  = 4;          // m16 tiles per warp (64 rows)
    constexpr int WNC = BN / 4;     // cols per warp
    constexpr int NTL = WNC / 8;    // n8 tiles per warp
    constexpr int ASZ = 128 * 80;   // bytes, one A operand tile (padded rows)
    constexpr int BSZ = BN * 80;
    constexpr int STAGE = 2 * ASZ + BSZ;

    extern __shared__ char smem[];
    const uint32_t sbase = smem_u32(smem);

    const int tid = threadIdx.x;
    const int wid = tid >> 5;
    const int lid = tid & 31;
    const int wr = wid >> 2;        // 0..1
    const int wc = wid & 3;         // 0..3
    const int g  = lid >> 2;
    const int t  = lid & 3;

    const int row0 = blockIdx.y * 128;
    const int col0 = blockIdx.x * BN;
    const int h    = blockIdx.x;    // head index (BN == head dim)

    float acc[MT][NTL][4];
#pragma unroll
    for (int m = 0; m < MT; m++)
#pragma unroll
        for (int n = 0; n < NTL; n++)
#pragma unroll
            for (int q = 0; q < 4; q++) acc[m][n][q] = 0.f;

    const int nch = K >> 5;

    auto ld_stage = [&](int s, int k0) {
        const uint32_t sb = sbase + s * STAGE;
#pragma unroll
        for (int c = tid; c < 512; c += 256) {
            int r = c >> 2, q = c & 3;
            int gr = row0 + r;
            bool ok = gr < M;
            size_t goff = (size_t)(ok ? gr : row0) * K + k0 + q * 8;
            cp16(sb + r * 80 + q * 16, Ahi + goff, ok);
            cp16(sb + ASZ + r * 80 + q * 16, Alo + goff, ok);
        }
#pragma unroll
        for (int c = tid; c < BN * 4; c += 256) {
            int r = c >> 2, q = c & 3;
            size_t goff = (size_t)(col0 + r) * K + k0 + q * 8;
            cp16(sb + 2 * ASZ + r * 80 + q * 16, Bh + goff, true);
        }
    };

    ld_stage(0, 0);
    cp_commit();
    ld_stage(1, 32);
    cp_commit();

    for (int i = 0; i < nch; i++) {
        if (i + 2 < nch) {
            ld_stage((i + 2) % 3, (i + 2) * 32);
            cp_commit();
            asm volatile("cp.async.wait_group 2;" ::: "memory");
        } else if (i + 1 < nch) {
            asm volatile("cp.async.wait_group 1;" ::: "memory");
        } else {
            asm volatile("cp.async.wait_group 0;" ::: "memory");
        }
        __syncthreads();

        const char* sA_hi = smem + (i % 3) * STAGE;
        const char* sA_lo = sA_hi + ASZ;
        const char* sB    = sA_lo + ASZ;

#pragma unroll
        for (int ks = 0; ks < 2; ks++) {
            const int kb = ks * 32 + t * 4;   // byte offset within padded row

            uint32_t bf[NTL][2];
#pragma unroll
            for (int n = 0; n < NTL; n++) {
                int off = (wc * WNC + n * 8 + g) * 80 + kb;
                bf[n][0] = *(const uint32_t*)(sB + off);
                bf[n][1] = *(const uint32_t*)(sB + off + 16);
            }
#pragma unroll
            for (int m = 0; m < MT; m++) {
                int off = (wr * 64 + m * 16 + g) * 80 + kb;
                uint32_t ah[4], al_[4];
                ah[0] = *(const uint32_t*)(sA_hi + off);
                ah[1] = *(const uint32_t*)(sA_hi + off + 640);
                ah[2] = *(const uint32_t*)(sA_hi + off + 16);
                ah[3] = *(const uint32_t*)(sA_hi + off + 656);
                al_[0] = *(const uint32_t*)(sA_lo + off);
                al_[1] = *(const uint32_t*)(sA_lo + off + 640);
                al_[2] = *(const uint32_t*)(sA_lo + off + 16);
                al_[3] = *(const uint32_t*)(sA_lo + off + 656);
#pragma unroll
                for (int n = 0; n < NTL; n++) {
                    mma_f16(acc[m][n], ah, bf[n]);
                    mma_f16(acc[m][n], al_, bf[n]);
                }
            }
        }
        __syncthreads();
    }

    // ---- Epilogue: bias add + C store + fused logit partial dots ----
    float alv[NTL][2], arv[NTL][2], bv[NTL][2];
#pragma unroll
    for (int n = 0; n < NTL; n++) {
        int cc = col0 + wc * WNC + n * 8 + t * 2;
        alv[n][0] = al[cc]; alv[n][1] = al[cc + 1];
        arv[n][0] = ar[cc]; arv[n][1] = ar[cc + 1];
        bv[n][0]  = bias[cc]; bv[n][1] = bias[cc + 1];
    }

#pragma unroll
    for (int m = 0; m < MT; m++) {
        int r0r = row0 + wr * 64 + m * 16 + g;
        int r1r = r0r + 8;
        float p1a = 0.f, p2a = 0.f, p1b = 0.f, p2b = 0.f;
#pragma unroll
        for (int n = 0; n < NTL; n++) {
            float c0 = acc[m][n][0] + bv[n][0];
            float c1 = acc[m][n][1] + bv[n][1];
            float c2 = acc[m][n][2] + bv[n][0];
            float c3 = acc[m][n][3] + bv[n][1];
            int cc = col0 + wc * WNC + n * 8 + t * 2;
            if (HALFOUT) {
                __half* Ch = (__half*)Cv;
                if (r0r < M)
                    *(__half2*)(Ch + (size_t)r0r * ldc + cc) = __floats2half2_rn(c0, c1);
                if (r1r < M)
                    *(__half2*)(Ch + (size_t)r1r * ldc + cc) = __floats2half2_rn(c2, c3);
            } else {
                float* Cf = (float*)Cv;
                if (r0r < M)
                    *(float2*)(Cf + (size_t)r0r * ldc + cc) = make_float2(c0, c1);
                if (r1r < M)
                    *(float2*)(Cf + (size_t)r1r * ldc + cc) = make_float2(c2, c3);
            }
            p1a = fmaf(c0, alv[n][0], fmaf(c1, alv[n][1], p1a));
            p2a = fmaf(c0, arv[n][0], fmaf(c1, arv[n][1], p2a));
            p1b = fmaf(c2, alv[n][0], fmaf(c3, alv[n][1], p1b));
            p2b = fmaf(c2, arv[n][0], fmaf(c3, arv[n][1], p2b));
        }
#pragma unroll
        for (int o = 1; o <= 2; o <<= 1) {
            p1a += __shfl_xor_sync(0xffffffffu, p1a, o);
            p2a += __shfl_xor_sync(0xffffffffu, p2a, o);
            p1b += __shfl_xor_sync(0xffffffffu, p1b, o);
            p2b += __shfl_xor_sync(0xffffffffu, p2b, o);
        }
        if (t == 0) {
            if (r0r < M) {
                atomicAdd(&a1g[r0r * Hn + h], p1a);
                atomicAdd(&a2g[r0r * Hn + h], p2a);
            }
            if (r1r < M) {
                atomicAdd(&a1g[r1r * Hn + h], p1b);
                atomicAdd(&a2g[r1r * Hn + h], p2b);
            }
        }
    }
}

// ---------------------------------------------------------------------------
// Edge-softmax + aggregation + ELU.  One warp per (node, head).
// HALFIN: gather fp16 ft (half traffic).  SPLIT: write fp16 hi/lo for next GEMM.
// Also initializes the NEXT layer's a1/a2 logit buffers with per-head consts
// (safe: reads use the current double-buffer, writes go to the other one).
// ---------------------------------------------------------------------------
template<int VEC, bool HALFIN, bool SPLIT>
__global__ void aggregate_kernel(const void* __restrict__ ftv,
                                 const float* __restrict__ a1,
                                 const float* __restrict__ a2,
                                 const int* __restrict__ rowptr,
                                 const int* __restrict__ srcs,
                                 float* __restrict__ out,
                                 __half* __restrict__ outHi,
                                 __half* __restrict__ outLo,
                                 const float* __restrict__ c1n,
                                 const float* __restrict__ c2n,
                                 float* __restrict__ a1n,
                                 float* __restrict__ a2n,
                                 int HnNext,
                                 int Nn, int Hn, int ld) {
    constexpr int HIDo = VEC * 32;
    int gw   = (blockIdx.x * blockDim.x + threadIdx.x) >> 5;
    int lane = threadIdx.x & 31;
    if (gw >= Nn * Hn) return;
    int n = gw / Hn;
    int h = gw - n * Hn;
    int beg = rowptr[n];
    int end = rowptr[n + 1];
    float a1v = a1[n * Hn + h];

    // pass 1: segment max of leaky-relu logits
    float m = -1e30f;
    for (int e = beg + lane; e < end; e += 32) {
        float s = a1v + a2[srcs[e] * Hn + h];
        s = (s >= 0.f) ? s : 0.01f * s;
        m = fmaxf(m, s);
    }
    for (int o = 16; o; o >>= 1) m = fmaxf(m, __shfl_xor_sync(0xffffffffu, m, o));

    // pass 2: fused denom + unnormalized weighted feature accumulation
    float acc[VEC];
#pragma unroll
    for (int r = 0; r < VEC; r++) acc[r] = 0.f;
    float den = 0.f;

    for (int e0 = beg; e0 < end; e0 += 32) {
        int e = e0 + lane;
        float ev = 0.f;
        int sv = 0;
        if (e < end) {
            sv = srcs[e];
            float s = a1v + a2[sv * Hn + h];
            s = (s >= 0.f) ? s : 0.01f * s;
            ev = __expf(s - m);
        }
        den += ev;
        int cnt = min(32, end - e0);
        for (int i = 0; i < cnt; i++) {
            float wi = __shfl_sync(0xffffffffu, ev, i);
            int   si = __shfl_sync(0xffffffffu, sv, i);
            if constexpr (HALFIN) {
                const __half* fp = (const __half*)ftv + (size_t)si * ld + h * HIDo;
                if (VEC == 4) {
                    uint2 raw = *((const uint2*)fp + lane);
                    __half2 p0 = *reinterpret_cast<__half2*>(&raw.x);
                    __half2 p1 = *reinterpret_cast<__half2*>(&raw.y);
                    float2 v01 = __half22float2(p0);
                    float2 v23 = __half22float2(p1);
                    acc[0] = fmaf(wi, v01.x, acc[0]);
                    acc[1] = fmaf(wi, v01.y, acc[1]);
                    acc[2] = fmaf(wi, v23.x, acc[2]);
                    acc[3] = fmaf(wi, v23.y, acc[3]);
                } else {
                    uint32_t raw = *((const uint32_t*)fp + lane);
                    __half2 p0 = *reinterpret_cast<__half2*>(&raw);
                    float2 v01 = __half22float2(p0);
                    acc[0] = fmaf(wi, v01.x, acc[0]);
                    acc[1] = fmaf(wi, v01.y, acc[1]);
                }
            } else {
                const float* fp = (const float*)ftv + (size_t)si * ld + h * HIDo;
                if (VEC == 4) {
                    float4 v = *((const float4*)fp + lane);
                    acc[0] = fmaf(wi, v.x, acc[0]);
                    acc[1] = fmaf(wi, v.y, acc[1]);
                    acc[2] = fmaf(wi, v.z, acc[2]);
                    acc[3] = fmaf(wi, v.w, acc[3]);
                } else {
                    float2 v = *((const float2*)fp + lane);
                    acc[0] = fmaf(wi, v.x, acc[0]);
                    acc[1] = fmaf(wi, v.y, acc[1]);
                }
            }
        }
    }
    for (int o = 16; o; o >>= 1) den += __shfl_xor_sync(0xffffffffu, den, o);
    float inv = 1.f / den;

    float r[VEC];
#pragma unroll
    for (int q = 0; q < VEC; q++) {
        float v = acc[q] * inv;
        r[q] = (v > 0.f) ? v : expm1f(v);
    }

    size_t ob = (size_t)n * ld + h * HIDo + lane * VEC;
    if constexpr (SPLIT) {
        __half hv[VEC], lv[VEC];
#pragma unroll
        for (int q = 0; q < VEC; q++) {
            hv[q] = __float2half_rn(r[q]);
            lv[q] = __float2half_rn(r[q] - __half2float(hv[q]));
        }
        if (VEC == 4) {
            *(__half2*)(outHi + ob)     = __halves2half2(hv[0], hv[1]);
            *(__half2*)(outHi + ob + 2) = __halves2half2(hv[2], hv[3]);
            *(__half2*)(outLo + ob)     = __halves2half2(lv[0], lv[1]);
            *(__half2*)(outLo + ob + 2) = __halves2half2(lv[2], lv[3]);
        } else {
            *(__half2*)(outHi + ob) = __halves2half2(hv[0], hv[1]);
            *(__half2*)(outLo + ob) = __halves2half2(lv[0], lv[1]);
        }
    } else {
        if (VEC == 4) {
            *(float4*)(out + ob) = make_float4(r[0], r[1], r[2], r[3]);
        } else {
            *(float2*)(out + ob) = make_float2(r[0], r[1]);
        }
    }

    // fused init of the NEXT layer's logit buffers (double-buffered, no race)
    if (a1n != nullptr && lane == 0 && h < HnNext) {
        a1n[n * HnNext + h] = c1n[h];
        a2n[n * HnNext + h] = c2n[h];
    }
}

// ---------------------------------------------------------------------------
// Host launch
// ---------------------------------------------------------------------------
extern "C" void kernel_launch(void* const* d_in, const int* in_sizes, int n_in,
                              void* d_out, int out_size) {
    const float* features = (const float*)d_in[0];
    const int*   src      = (const int*)d_in[1];
    const int*   dst      = (const int*)d_in[2];
    const float* W0  = (const float*)d_in[3];
    const float* b0  = (const float*)d_in[4];
    const float* al0 = (const float*)d_in[5];
    const float* alb0= (const float*)d_in[6];
    const float* ar0 = (const float*)d_in[7];
    const float* arb0= (const float*)d_in[8];
    const float* W1  = (const float*)d_in[9];
    const float* b1  = (const float*)d_in[10];
    const float* al1 = (const float*)d_in[11];
    const float* alb1= (const float*)d_in[12];
    const float* ar1 = (const float*)d_in[13];
    const float* arb1= (const float*)d_in[14];
    const float* Wf  = (const float*)d_in[15];
    const float* bfv = (const float*)d_in[16];
    const float* alf = (const float*)d_in[17];
    const float* albf= (const float*)d_in[18];
    const float* arf = (const float*)d_in[19];
    const float* arbf= (const float*)d_in[20];

    float *ft, *a1a, *a2a, *a1b, *a2b, *c1, *c2;
    __half *Ahi, *Alo, *Bh;
    int *cnt, *rowptr, *cursor, *ssrc;
    cudaGetSymbolAddress((void**)&ft,  g_ft);
    cudaGetSymbolAddress((void**)&Ahi, g_Ahi);
    cudaGetSymbolAddress((void**)&Alo, g_Alo);
    cudaGetSymbolAddress((void**)&Bh,  g_Bh);
    cudaGetSymbolAddress((void**)&a1a, g_a1a);
    cudaGetSymbolAddress((void**)&a2a, g_a2a);
    cudaGetSymbolAddress((void**)&a1b, g_a1b);
    cudaGetSymbolAddress((void**)&a2b, g_a2b);
    cudaGetSymbolAddress((void**)&c1, g_c1);
    cudaGetSymbolAddress((void**)&c2, g_c2);
    cudaGetSymbolAddress((void**)&cnt, g_cnt);
    cudaGetSymbolAddress((void**)&rowptr, g_rowptr);
    cudaGetSymbolAddress((void**)&cursor, g_cursor);
    cudaGetSymbolAddress((void**)&ssrc, g_srcsorted);

    __half* fth = (__half*)ft;   // fp16 alias of the ft buffer (mid layers)

    // SMEM: 3 stages * (2*A(128*80) + B(BN*80))
    constexpr int SMEM128 = 3 * (2 * 128 * 80 + 128 * 80);  // 92160
    constexpr int SMEM64  = 3 * (2 * 128 * 80 + 64 * 80);   // 76800
    cudaFuncSetAttribute(gemm_mma_kernel<128, true>,
                         cudaFuncAttributeMaxDynamicSharedMemorySize, SMEM128);
    cudaFuncSetAttribute(gemm_mma_kernel<64, false>,
                         cudaFuncAttributeMaxDynamicSharedMemorySize, SMEM64);

    // --- CSR build ---
    zero_int_kernel<<<(cN + 255) / 256, 256>>>(cnt, cN);
    hist_kernel<<<(cE + 255) / 256, 256>>>(dst, cnt, cE);
    scan_kernel<<<1, 1024>>>(cnt, rowptr, cursor, cN);
    scatter_kernel<<<(cE + 255) / 256, 256>>>(src, dst, cursor, ssrc, cE);

    const int gridM = (cN + 127) / 128;   // 157
    const int warpBlocksH = (cN * cH * 32 + 255) / 256;
    const int warpBlocks1 = (cN * 32 + 255) / 256;

    // --- logit constants for all 3 layers ---
    logit_const_kernel<<<1, 256>>>(b0, al0, alb0, ar0, arb0, c1, c2, cH, cHID);
    logit_const_kernel<<<1, 256>>>(b1, al1, alb1, ar1, arb1, c1 + cH, c2 + cH, cH, cHID);
    logit_const_kernel<<<1, 32>>>(bfv, alf, albf, arf, arbf, c1 + 2 * cH, c2 + 2 * cH, 1, cC);

    // --- layer 0 ---
    split_kernel<<<(cN * cIN / 4 + 255) / 256, 256>>>(features, Ahi, Alo, cN * cIN / 4);
    wprep_kernel<<<(cHH * cIN + 255) / 256, 256>>>(W0, Bh, cIN, cHID, cHH * cIN);
    logit_init_kernel<<<(cN * cH + 255) / 256, 256>>>(c1, c2, a1a, a2a, cN * cH, cH);
    gemm_mma_kernel<128, true><<<dim3(8, gridM), 256, SMEM128>>>(
        Ahi, Alo, Bh, b0, al0, ar0, a1a, a2a, fth, cN, cIN, cHH, cH);
    aggregate_kernel<4, true, true><<<warpBlocksH, 256>>>(
        fth, a1a, a2a, rowptr, ssrc, nullptr, Ahi, Alo,
        c1 + cH, c2 + cH, a1b, a2b, cH, cN, cH, cHH);

    // --- layer 1 ---
    wprep_kernel<<<(cHH * cHH + 255) / 256, 256>>>(W1, Bh, cHH, cHID, cHH * cHH);
    gemm_mma_kernel<128, true><<<dim3(8, gridM), 256, SMEM128>>>(
        Ahi, Alo, Bh, b1, al1, ar1, a1b, a2b, fth, cN, cHH, cHH, cH);
    aggregate_kernel<4, true, true><<<warpBlocksH, 256>>>(
        fth, a1b, a2b, rowptr, ssrc, nullptr, Ahi, Alo,
        c1 + 2 * cH, c2 + 2 * cH, a1a, a2a, 1, cN, cH, cHH);

    // --- final layer ---
    wprep_kernel<<<(cC * cHH + 255) / 256, 256>>>(Wf, Bh, cHH, cC, cC * cHH);
    gemm_mma_kernel<64, false><<<dim3(1, gridM), 256, SMEM64>>>(
        Ahi, Alo, Bh, bfv, alf, arf, a1a, a2a, ft, cN, cHH, cC, 1);
    aggregate_kernel<2, false, false><<<warpBlocks1, 256>>>(
        ft, a1a, a2a, rowptr, ssrc, (float*)d_out, nullptr, nullptr,
        nullptr, nullptr, nullptr, nullptr, 0, cN, 1, cC);
}

// round 9
// speedup vs baseline: 1.5928x; 1.0178x over previous
#include <cuda_runtime.h>
#include <cuda_fp16.h>
#include <math.h>
#include <stdint.h>

// Problem constants (fixed by the dataset)
constexpr int cN   = 20000;
constexpr int cE   = 320000;
constexpr int cIN  = 512;
constexpr int cHID = 128;
constexpr int cH   = 8;
constexpr int cC   = 64;
constexpr int cHH  = cH * cHID;   // 1024

// ---------------------------------------------------------------------------
// Scratch (static __device__ globals; no allocation allowed)
// ---------------------------------------------------------------------------
__device__ __align__(128) float  g_ft[(size_t)cN * cHH];   // GEMM out (fp32 or fp16 alias)
__device__ __align__(128) __half g_Ahi[(size_t)cN * cHH];  // A hi split (fp16)
__device__ __align__(128) __half g_Alo[(size_t)cN * cHH];  // A lo split (fp16)
__device__ __align__(128) __half g_Bh[cHH * cHH];          // W fp16, [Nout][K]
__device__ float g_a1a[cN * cH];
__device__ float g_a2a[cN * cH];
__device__ float g_a1b[cN * cH];
__device__ float g_a2b[cN * cH];
__device__ float g_c1[3 * cH];    // per-layer, per-head logit constants
__device__ float g_c2[3 * cH];
__device__ int   g_cnt[cN];
__device__ int   g_rowptr[cN + 1];
__device__ int   g_cursor[cN];
__device__ int   g_srcsorted[cE];

// ---------------------------------------------------------------------------
// PTX helpers (base sm_80+ ISA only — harness lowers to plain sm_103)
// ---------------------------------------------------------------------------
__device__ __forceinline__ uint32_t smem_u32(const void* p) {
    uint32_t a;
    asm("{ .reg .u64 t; cvta.to.shared.u64 t, %1; cvt.u32.u64 %0, t; }" : "=r"(a) : "l"(p));
    return a;
}
__device__ __forceinline__ void cp16(uint32_t dst, const void* src, bool ok) {
    int sz = ok ? 16 : 0;
    asm volatile("cp.async.cg.shared.global [%0], [%1], 16, %2;"
                 :: "r"(dst), "l"(src), "r"(sz) : "memory");
}
__device__ __forceinline__ void cp_commit() {
    asm volatile("cp.async.commit_group;" ::: "memory");
}
__device__ __forceinline__ void mma_f16(float* d, const uint32_t* a, const uint32_t* b) {
    asm volatile(
        "mma.sync.aligned.m16n8k16.row.col.f32.f16.f16.f32 "
        "{%0,%1,%2,%3}, {%4,%5,%6,%7}, {%8,%9}, {%0,%1,%2,%3};"
        : "+f"(d[0]), "+f"(d[1]), "+f"(d[2]), "+f"(d[3])
        : "r"(a[0]), "r"(a[1]), "r"(a[2]), "r"(a[3]), "r"(b[0]), "r"(b[1]));
}
__device__ __forceinline__ void ldsm_x4(uint32_t* r, uint32_t addr) {
    asm volatile("ldmatrix.sync.aligned.m8n8.x4.shared.b16 {%0,%1,%2,%3}, [%4];"
                 : "=r"(r[0]), "=r"(r[1]), "=r"(r[2]), "=r"(r[3]) : "r"(addr));
}
__device__ __forceinline__ void ldsm_x2(uint32_t* r, uint32_t addr) {
    asm volatile("ldmatrix.sync.aligned.m8n8.x2.shared.b16 {%0,%1}, [%2];"
                 : "=r"(r[0]), "=r"(r[1]) : "r"(addr));
}

// ---------------------------------------------------------------------------
// CSR build
// ---------------------------------------------------------------------------
__global__ void zero_int_kernel(int* p, int n) {
    int i = blockIdx.x * blockDim.x + threadIdx.x;
    if (i < n) p[i] = 0;
}
__global__ void hist_kernel(const int* __restrict__ dst, int* __restrict__ cnt, int e) {
    int i = blockIdx.x * blockDim.x + threadIdx.x;
    if (i < e) atomicAdd(&cnt[dst[i]], 1);
}
__global__ void scan_kernel(const int* __restrict__ cnt, int* __restrict__ rowptr,
                            int* __restrict__ cursor, int n) {
    __shared__ int sh[1024];
    int tid = threadIdx.x;
    const int CH = (n + 1023) / 1024;
    int st = tid * CH;
    int s = 0;
    for (int i = 0; i < CH; i++) {
        int idx = st + i;
        if (idx < n) s += cnt[idx];
    }
    sh[tid] = s;
    __syncthreads();
    for (int d = 1; d < 1024; d <<= 1) {
        int v = (tid >= d) ? sh[tid - d] : 0;
        __syncthreads();
        sh[tid] += v;
        __syncthreads();
    }
    int run = sh[tid] - s;
    for (int i = 0; i < CH; i++) {
        int idx = st + i;
        if (idx < n) {
            rowptr[idx] = run;
            cursor[idx] = run;
            run += cnt[idx];
        }
    }
    if (tid == 1023) rowptr[n] = sh[1023];
}
__global__ void scatter_kernel(const int* __restrict__ src, const int* __restrict__ dst,
                               int* __restrict__ cursor, int* __restrict__ out, int e) {
    int i = blockIdx.x * blockDim.x + threadIdx.x;
    if (i < e) {
        int d = dst[i];
        int pos = atomicAdd(&cursor[d], 1);
        out[pos] = src[i];
    }
}

// ---------------------------------------------------------------------------
// fp32 -> fp16 hi/lo split (first-layer features), float4 vectorized
// ---------------------------------------------------------------------------
__global__ void split_kernel(const float* __restrict__ in,
                             __half* __restrict__ hi,
                             __half* __restrict__ lo, int n4) {
    int i = blockIdx.x * blockDim.x + threadIdx.x;
    if (i >= n4) return;
    float4 v = ((const float4*)in)[i];
    __half h0 = __float2half_rn(v.x), h1 = __float2half_rn(v.y);
    __half h2 = __float2half_rn(v.z), h3 = __float2half_rn(v.w);
    __half l0 = __float2half_rn(v.x - __half2float(h0));
    __half l1 = __float2half_rn(v.y - __half2float(h1));
    __half l2 = __float2half_rn(v.z - __half2float(h2));
    __half l3 = __float2half_rn(v.w - __half2float(h3));
    ((__half2*)hi)[i * 2]     = __halves2half2(h0, h1);
    ((__half2*)hi)[i * 2 + 1] = __halves2half2(h2, h3);
    ((__half2*)lo)[i * 2]     = __halves2half2(l0, l1);
    ((__half2*)lo)[i * 2 + 1] = __halves2half2(l2, l3);
}

// ---------------------------------------------------------------------------
// Weight prep via SMEM tile transpose (coalesced both sides):
// W [h][k][j] (j contiguous) -> B [n = h*HIDo + j][k] fp16
// Block (32,8), tile 32x32, grid (K/32, HIDo/32, H).
// ---------------------------------------------------------------------------
__global__ void wprep_t_kernel(const float* __restrict__ W,
                               __half* __restrict__ Bh, int K, int HIDo) {
    __shared__ __half tile[32][33];
    int h  = blockIdx.z;
    int k0 = blockIdx.x * 32;
    int j0 = blockIdx.y * 32;
    const float* Wp = W + (size_t)h * K * HIDo;
    int tx = threadIdx.x, ty = threadIdx.y;
#pragma unroll
    for (int i = 0; i < 32; i += 8)
        tile[ty + i][tx] = __float2half_rn(Wp[(size_t)(k0 + ty + i) * HIDo + j0 + tx]);
    __syncthreads();
#pragma unroll
    for (int i = 0; i < 32; i += 8)
        Bh[(size_t)(h * HIDo + j0 + ty + i) * K + k0 + tx] = tile[tx][ty + i];
}

// ---------------------------------------------------------------------------
// Per-head logit constants: c1[h] = alb[h] + dot(bias_head, al_head)
// ---------------------------------------------------------------------------
__global__ void logit_const_kernel(const float* __restrict__ bias,
                                   const float* __restrict__ al,
                                   const float* __restrict__ alb,
                                   const float* __restrict__ ar,
                                   const float* __restrict__ arb,
                                   float* __restrict__ c1, float* __restrict__ c2,
                                   int Hn, int HIDo) {
    int h = threadIdx.x >> 5;
    int lane = threadIdx.x & 31;
    if (h >= Hn) return;
    float s1 = 0.f, s2 = 0.f;
    for (int j = lane; j < HIDo; j += 32) {
        float b = bias[h * HIDo + j];
        s1 = fmaf(b, al[h * HIDo + j], s1);
        s2 = fmaf(b, ar[h * HIDo + j], s2);
    }
    for (int o = 16; o; o >>= 1) {
        s1 += __shfl_xor_sync(0xffffffffu, s1, o);
        s2 += __shfl_xor_sync(0xffffffffu, s2, o);
    }
    if (lane == 0) {
        c1[h] = s1 + alb[h];
        c2[h] = s2 + arb[h];
    }
}

__global__ void logit_init_kernel(const float* __restrict__ c1,
                                  const float* __restrict__ c2,
                                  float* __restrict__ a1, float* __restrict__ a2,
                                  int total, int Hn) {
    int i = blockIdx.x * blockDim.x + threadIdx.x;
    if (i >= total) return;
    int h = i % Hn;
    a1[i] = c1[h];
    a2[i] = c2[h];
}

// ---------------------------------------------------------------------------
// 2-term fp16 warp-MMA GEMM with fused bias + fused attention-logit dots.
//   C = A(fp32 as hi/lo fp16) @ W(fp16)^T,  D = Ahi*B + Alo*B (fp32 acc)
// Fragments loaded with ldmatrix (x4 for A, x2 for B) — 80B padded rows are
// conflict-free (bank(r) = 20r mod 32, all distinct over 8 rows).
// Tile: BM=128 x BN x BK=32, 8 warps (2x4), 3-stage cp.async pipeline.
// HALFOUT: write C as fp16 (feeds fp16-gather aggregate).
// Epilogue: bias add + C store + per-row a1/a2 partial dots -> atomicAdd.
// ---------------------------------------------------------------------------
template<int BN, bool HALFOUT>
__global__ __launch_bounds__(256, 2)
void gemm_mma_kernel(const __half* __restrict__ Ahi,
                     const __half* __restrict__ Alo,
                     const __half* __restrict__ Bh,
                     const float* __restrict__ bias,
                     const float* __restrict__ al,
                     const float* __restrict__ ar,
                     float* __restrict__ a1g,
                     float* __restrict__ a2g,
                     void* __restrict__ Cv,
                     int M, int K, int ldc, int Hn) {
    constexpr int MT  = 4;          // m16 tiles per warp (64 rows)
    constexpr int WNC = BN / 4;     // cols per warp
    constexpr int NTL = WNC / 8;    // n8 tiles per warp
    constexpr int ASZ = 128 * 80;   // bytes, one A operand tile (padded rows)
    constexpr int BSZ = BN * 80;
    constexpr int STAGE = 2 * ASZ + BSZ;

    extern __shared__ char smem[];
    const uint32_t sbase = smem_u32(smem);

    const int tid = threadIdx.x;
    const int wid = tid >> 5;
    const int lid = tid & 31;
    const int wr = wid >> 2;        // 0..1
    const int wc = wid & 3;         // 0..3
    const int g  = lid >> 2;
    const int t  = lid & 3;

    const int row0 = blockIdx.y * 128;
    const int col0 = blockIdx.x * BN;
    const int h    = blockIdx.x;    // head index (BN == head dim)

    // ldmatrix per-lane in-tile offsets
    const int lr = lid & 7;
    const uint32_t aOff = (uint32_t)(wr * 64 + ((lid >> 3) & 1) * 8 + lr) * 80
                        + (uint32_t)(lid >> 4) * 16;
    const uint32_t bOff = (uint32_t)(wc * WNC + lr) * 80
                        + (uint32_t)((lid >> 3) & 1) * 16;

    float acc[MT][NTL][4];
#pragma unroll
    for (int m = 0; m < MT; m++)
#pragma unroll
        for (int n = 0; n < NTL; n++)
#pragma unroll
            for (int q = 0; q < 4; q++) acc[m][n][q] = 0.f;

    const int nch = K >> 5;

    auto ld_stage = [&](int s, int k0) {
        const uint32_t sb = sbase + s * STAGE;
#pragma unroll
        for (int c = tid; c < 512; c += 256) {
            int r = c >> 2, q = c & 3;
            int gr = row0 + r;
            bool ok = gr < M;
            size_t goff = (size_t)(ok ? gr : row0) * K + k0 + q * 8;
            cp16(sb + r * 80 + q * 16, Ahi + goff, ok);
            cp16(sb + ASZ + r * 80 + q * 16, Alo + goff, ok);
        }
#pragma unroll
        for (int c = tid; c < BN * 4; c += 256) {
            int r = c >> 2, q = c & 3;
            size_t goff = (size_t)(col0 + r) * K + k0 + q * 8;
            cp16(sb + 2 * ASZ + r * 80 + q * 16, Bh + goff, true);
        }
    };

    ld_stage(0, 0);
    cp_commit();
    ld_stage(1, 32);
    cp_commit();

    for (int i = 0; i < nch; i++) {
        if (i + 2 < nch) {
            ld_stage((i + 2) % 3, (i + 2) * 32);
            cp_commit();
            asm volatile("cp.async.wait_group 2;" ::: "memory");
        } else if (i + 1 < nch) {
            asm volatile("cp.async.wait_group 1;" ::: "memory");
        } else {
            asm volatile("cp.async.wait_group 0;" ::: "memory");
        }
        __syncthreads();

        const uint32_t sAh = sbase + (i % 3) * STAGE;
        const uint32_t sAl = sAh + ASZ;
        const uint32_t sB  = sAl + ASZ;

#pragma unroll
        for (int ks = 0; ks < 2; ks++) {
            const uint32_t kcol = ks * 32;

            uint32_t bf[NTL][2];
#pragma unroll
            for (int n = 0; n < NTL; n++)
                ldsm_x2(bf[n], sB + bOff + n * (8 * 80) + kcol);
#pragma unroll
            for (int m = 0; m < MT; m++) {
                uint32_t ah[4], al_[4];
                ldsm_x4(ah,  sAh + aOff + m * (16 * 80) + kcol);
                ldsm_x4(al_, sAl + aOff + m * (16 * 80) + kcol);
#pragma unroll
                for (int n = 0; n < NTL; n++) {
                    mma_f16(acc[m][n], ah, bf[n]);
                    mma_f16(acc[m][n], al_, bf[n]);
                }
            }
        }
        __syncthreads();
    }

    // ---- Epilogue: bias add + C store + fused logit partial dots ----
    float alv[NTL][2], arv[NTL][2], bv[NTL][2];
#pragma unroll
    for (int n = 0; n < NTL; n++) {
        int cc = col0 + wc * WNC + n * 8 + t * 2;
        alv[n][0] = al[cc]; alv[n][1] = al[cc + 1];
        arv[n][0] = ar[cc]; arv[n][1] = ar[cc + 1];
        bv[n][0]  = bias[cc]; bv[n][1] = bias[cc + 1];
    }

#pragma unroll
    for (int m = 0; m < MT; m++) {
        int r0r = row0 + wr * 64 + m * 16 + g;
        int r1r = r0r + 8;
        float p1a = 0.f, p2a = 0.f, p1b = 0.f, p2b = 0.f;
#pragma unroll
        for (int n = 0; n < NTL; n++) {
            float c0 = acc[m][n][0] + bv[n][0];
            float c1 = acc[m][n][1] + bv[n][1];
            float c2 = acc[m][n][2] + bv[n][0];
            float c3 = acc[m][n][3] + bv[n][1];
            int cc = col0 + wc * WNC + n * 8 + t * 2;
            if (HALFOUT) {
                __half* Ch = (__half*)Cv;
                if (r0r < M)
                    *(__half2*)(Ch + (size_t)r0r * ldc + cc) = __floats2half2_rn(c0, c1);
                if (r1r < M)
                    *(__half2*)(Ch + (size_t)r1r * ldc + cc) = __floats2half2_rn(c2, c3);
            } else {
                float* Cf = (float*)Cv;
                if (r0r < M)
                    *(float2*)(Cf + (size_t)r0r * ldc + cc) = make_float2(c0, c1);
                if (r1r < M)
                    *(float2*)(Cf + (size_t)r1r * ldc + cc) = make_float2(c2, c3);
            }
            p1a = fmaf(c0, alv[n][0], fmaf(c1, alv[n][1], p1a));
            p2a = fmaf(c0, arv[n][0], fmaf(c1, arv[n][1], p2a));
            p1b = fmaf(c2, alv[n][0], fmaf(c3, alv[n][1], p1b));
            p2b = fmaf(c2, arv[n][0], fmaf(c3, arv[n][1], p2b));
        }
#pragma unroll
        for (int o = 1; o <= 2; o <<= 1) {
            p1a += __shfl_xor_sync(0xffffffffu, p1a, o);
            p2a += __shfl_xor_sync(0xffffffffu, p2a, o);
            p1b += __shfl_xor_sync(0xffffffffu, p1b, o);
            p2b += __shfl_xor_sync(0xffffffffu, p2b, o);
        }
        if (t == 0) {
            if (r0r < M) {
                atomicAdd(&a1g[r0r * Hn + h], p1a);
                atomicAdd(&a2g[r0r * Hn + h], p2a);
            }
            if (r1r < M) {
                atomicAdd(&a1g[r1r * Hn + h], p1b);
                atomicAdd(&a2g[r1r * Hn + h], p2b);
            }
        }
    }
}

// ---------------------------------------------------------------------------
// Edge-softmax + aggregation + ELU — single-pass ONLINE softmax.
// One warp per (node, head). Per 32-edge batch: batch max -> rescale running
// den/acc -> accumulate unnormalized exp-weighted gather. Mathematically
// identical to two-pass max-then-sum.
// HALFIN: gather fp16 ft.  SPLIT: write fp16 hi/lo for next GEMM.
// Also initializes NEXT layer's a1/a2 buffers (double-buffered, race-free).
// ---------------------------------------------------------------------------
template<int VEC, bool HALFIN, bool SPLIT>
__global__ void aggregate_kernel(const void* __restrict__ ftv,
                                 const float* __restrict__ a1,
                                 const float* __restrict__ a2,
                                 const int* __restrict__ rowptr,
                                 const int* __restrict__ srcs,
                                 float* __restrict__ out,
                                 __half* __restrict__ outHi,
                                 __half* __restrict__ outLo,
                                 const float* __restrict__ c1n,
                                 const float* __restrict__ c2n,
                                 float* __restrict__ a1n,
                                 float* __restrict__ a2n,
                                 int HnNext,
                                 int Nn, int Hn, int ld) {
    constexpr int HIDo = VEC * 32;
    int gw   = (blockIdx.x * blockDim.x + threadIdx.x) >> 5;
    int lane = threadIdx.x & 31;
    if (gw >= Nn * Hn) return;
    int n = gw / Hn;
    int h = gw - n * Hn;
    int beg = rowptr[n];
    int end = rowptr[n + 1];
    float a1v = a1[n * Hn + h];

    float m = -1e30f, den = 0.f;
    float acc[VEC];
#pragma unroll
    for (int r = 0; r < VEC; r++) acc[r] = 0.f;

    for (int e0 = beg; e0 < end; e0 += 32) {
        int e = e0 + lane;
        float s = -1e30f;
        int sv = 0;
        if (e < end) {
            sv = srcs[e];
            float x = a1v + a2[sv * Hn + h];
            s = (x >= 0.f) ? x : 0.01f * x;
        }
        // batch max -> rescale running state
        float bm = s;
        for (int o = 16; o; o >>= 1) bm = fmaxf(bm, __shfl_xor_sync(0xffffffffu, bm, o));
        float nm = fmaxf(m, bm);
        float scale = __expf(m - nm);   // 0 on first batch (m = -1e30)
        den *= scale;
#pragma unroll
        for (int r = 0; r < VEC; r++) acc[r] *= scale;
        m = nm;

        float ev = __expf(s - nm);      // 0 for out-of-range lanes
        den += ev;

        int cnt = min(32, end - e0);
        for (int i = 0; i < cnt; i++) {
            float wi = __shfl_sync(0xffffffffu, ev, i);
            int   si = __shfl_sync(0xffffffffu, sv, i);
            if constexpr (HALFIN) {
                const __half* fp = (const __half*)ftv + (size_t)si * ld + h * HIDo;
                if (VEC == 4) {
                    uint2 raw = *((const uint2*)fp + lane);
                    float2 v01 = __half22float2(*reinterpret_cast<__half2*>(&raw.x));
                    float2 v23 = __half22float2(*reinterpret_cast<__half2*>(&raw.y));
                    acc[0] = fmaf(wi, v01.x, acc[0]);
                    acc[1] = fmaf(wi, v01.y, acc[1]);
                    acc[2] = fmaf(wi, v23.x, acc[2]);
                    acc[3] = fmaf(wi, v23.y, acc[3]);
                } else {
                    uint32_t raw = *((const uint32_t*)fp + lane);
                    float2 v01 = __half22float2(*reinterpret_cast<__half2*>(&raw));
                    acc[0] = fmaf(wi, v01.x, acc[0]);
                    acc[1] = fmaf(wi, v01.y, acc[1]);
                }
            } else {
                const float* fp = (const float*)ftv + (size_t)si * ld + h * HIDo;
                if (VEC == 4) {
                    float4 v = *((const float4*)fp + lane);
                    acc[0] = fmaf(wi, v.x, acc[0]);
                    acc[1] = fmaf(wi, v.y, acc[1]);
                    acc[2] = fmaf(wi, v.z, acc[2]);
                    acc[3] = fmaf(wi, v.w, acc[3]);
                } else {
                    float2 v = *((const float2*)fp + lane);
                    acc[0] = fmaf(wi, v.x, acc[0]);
                    acc[1] = fmaf(wi, v.y, acc[1]);
                }
            }
        }
    }
    for (int o = 16; o; o >>= 1) den += __shfl_xor_sync(0xffffffffu, den, o);
    float inv = 1.f / den;

    float r[VEC];
#pragma unroll
    for (int q = 0; q < VEC; q++) {
        float v = acc[q] * inv;
        r[q] = (v > 0.f) ? v : expm1f(v);
    }

    size_t ob = (size_t)n * ld + h * HIDo + lane * VEC;
    if constexpr (SPLIT) {
        __half hv[VEC], lv[VEC];
#pragma unroll
        for (int q = 0; q < VEC; q++) {
            hv[q] = __float2half_rn(r[q]);
            lv[q] = __float2half_rn(r[q] - __half2float(hv[q]));
        }
        if (VEC == 4) {
            *(__half2*)(outHi + ob)     = __halves2half2(hv[0], hv[1]);
            *(__half2*)(outHi + ob + 2) = __halves2half2(hv[2], hv[3]);
            *(__half2*)(outLo + ob)     = __halves2half2(lv[0], lv[1]);
            *(__half2*)(outLo + ob + 2) = __halves2half2(lv[2], lv[3]);
        } else {
            *(__half2*)(outHi + ob) = __halves2half2(hv[0], hv[1]);
            *(__half2*)(outLo + ob) = __halves2half2(lv[0], lv[1]);
        }
    } else {
        if (VEC == 4) {
            *(float4*)(out + ob) = make_float4(r[0], r[1], r[2], r[3]);
        } else {
            *(float2*)(out + ob) = make_float2(r[0], r[1]);
        }
    }

    // fused init of the NEXT layer's logit buffers (double-buffered, no race)
    if (a1n != nullptr && lane == 0 && h < HnNext) {
        a1n[n * HnNext + h] = c1n[h];
        a2n[n * HnNext + h] = c2n[h];
    }
}

// ---------------------------------------------------------------------------
// Host launch
// ---------------------------------------------------------------------------
extern "C" void kernel_launch(void* const* d_in, const int* in_sizes, int n_in,
                              void* d_out, int out_size) {
    const float* features = (const float*)d_in[0];
    const int*   src      = (const int*)d_in[1];
    const int*   dst      = (const int*)d_in[2];
    const float* W0  = (const float*)d_in[3];
    const float* b0  = (const float*)d_in[4];
    const float* al0 = (const float*)d_in[5];
    const float* alb0= (const float*)d_in[6];
    const float* ar0 = (const float*)d_in[7];
    const float* arb0= (const float*)d_in[8];
    const float* W1  = (const float*)d_in[9];
    const float* b1  = (const float*)d_in[10];
    const float* al1 = (const float*)d_in[11];
    const float* alb1= (const float*)d_in[12];
    const float* ar1 = (const float*)d_in[13];
    const float* arb1= (const float*)d_in[14];
    const float* Wf  = (const float*)d_in[15];
    const float* bfv = (const float*)d_in[16];
    const float* alf = (const float*)d_in[17];
    const float* albf= (const float*)d_in[18];
    const float* arf = (const float*)d_in[19];
    const float* arbf= (const float*)d_in[20];

    float *ft, *a1a, *a2a, *a1b, *a2b, *c1, *c2;
    __half *Ahi, *Alo, *Bh;
    int *cnt, *rowptr, *cursor, *ssrc;
    cudaGetSymbolAddress((void**)&ft,  g_ft);
    cudaGetSymbolAddress((void**)&Ahi, g_Ahi);
    cudaGetSymbolAddress((void**)&Alo, g_Alo);
    cudaGetSymbolAddress((void**)&Bh,  g_Bh);
    cudaGetSymbolAddress((void**)&a1a, g_a1a);
    cudaGetSymbolAddress((void**)&a2a, g_a2a);
    cudaGetSymbolAddress((void**)&a1b, g_a1b);
    cudaGetSymbolAddress((void**)&a2b, g_a2b);
    cudaGetSymbolAddress((void**)&c1, g_c1);
    cudaGetSymbolAddress((void**)&c2, g_c2);
    cudaGetSymbolAddress((void**)&cnt, g_cnt);
    cudaGetSymbolAddress((void**)&rowptr, g_rowptr);
    cudaGetSymbolAddress((void**)&cursor, g_cursor);
    cudaGetSymbolAddress((void**)&ssrc, g_srcsorted);

    __half* fth = (__half*)ft;   // fp16 alias of the ft buffer (mid layers)

    // SMEM: 3 stages * (2*A(128*80) + B(BN*80))
    constexpr int SMEM128 = 3 * (2 * 128 * 80 + 128 * 80);  // 92160
    constexpr int SMEM64  = 3 * (2 * 128 * 80 + 64 * 80);   // 76800
    cudaFuncSetAttribute(gemm_mma_kernel<128, true>,
                         cudaFuncAttributeMaxDynamicSharedMemorySize, SMEM128);
    cudaFuncSetAttribute(gemm_mma_kernel<64, false>,
                         cudaFuncAttributeMaxDynamicSharedMemorySize, SMEM64);

    // --- CSR build ---
    zero_int_kernel<<<(cN + 255) / 256, 256>>>(cnt, cN);
    hist_kernel<<<(cE + 255) / 256, 256>>>(dst, cnt, cE);
    scan_kernel<<<1, 1024>>>(cnt, rowptr, cursor, cN);
    scatter_kernel<<<(cE + 255) / 256, 256>>>(src, dst, cursor, ssrc, cE);

    const int gridM = (cN + 127) / 128;   // 157
    const int warpBlocksH = (cN * cH * 32 + 255) / 256;
    const int warpBlocks1 = (cN * 32 + 255) / 256;

    // --- logit constants for all 3 layers ---
    logit_const_kernel<<<1, 256>>>(b0, al0, alb0, ar0, arb0, c1, c2, cH, cHID);
    logit_const_kernel<<<1, 256>>>(b1, al1, alb1, ar1, arb1, c1 + cH, c2 + cH, cH, cHID);
    logit_const_kernel<<<1, 32>>>(bfv, alf, albf, arf, arbf, c1 + 2 * cH, c2 + 2 * cH, 1, cC);

    // --- layer 0 ---
    split_kernel<<<(cN * cIN / 4 + 255) / 256, 256>>>(features, Ahi, Alo, cN * cIN / 4);
    wprep_t_kernel<<<dim3(cIN / 32, cHID / 32, cH), dim3(32, 8)>>>(W0, Bh, cIN, cHID);
    logit_init_kernel<<<(cN * cH + 255) / 256, 256>>>(c1, c2, a1a, a2a, cN * cH, cH);
    gemm_mma_kernel<128, true><<<dim3(8, gridM), 256, SMEM128>>>(
        Ahi, Alo, Bh, b0, al0, ar0, a1a, a2a, fth, cN, cIN, cHH, cH);
    aggregate_kernel<4, true, true><<<warpBlocksH, 256>>>(
        fth, a1a, a2a, rowptr, ssrc, nullptr, Ahi, Alo,
        c1 + cH, c2 + cH, a1b, a2b, cH, cN, cH, cHH);

    // --- layer 1 ---
    wprep_t_kernel<<<dim3(cHH / 32, cHID / 32, cH), dim3(32, 8)>>>(W1, Bh, cHH, cHID);
    gemm_mma_kernel<128, true><<<dim3(8, gridM), 256, SMEM128>>>(
        Ahi, Alo, Bh, b1, al1, ar1, a1b, a2b, fth, cN, cHH, cHH, cH);
    aggregate_kernel<4, true, true><<<warpBlocksH, 256>>>(
        fth, a1b, a2b, rowptr, ssrc, nullptr, Ahi, Alo,
        c1 + 2 * cH, c2 + 2 * cH, a1a, a2a, 1, cN, cH, cHH);

    // --- final layer ---
    wprep_t_kernel<<<dim3(cHH / 32, cC / 32, 1), dim3(32, 8)>>>(Wf, Bh, cHH, cC);
    gemm_mma_kernel<64, false><<<dim3(1, gridM), 256, SMEM64>>>(
        Ahi, Alo, Bh, bfv, alf, arf, a1a, a2a, ft, cN, cHH, cC, 1);
    aggregate_kernel<2, false, false><<<warpBlocks1, 256>>>(
        ft, a1a, a2a, rowptr, ssrc, (float*)d_out, nullptr, nullptr,
        nullptr, nullptr, nullptr, nullptr, 0, cN, 1, cC);
}

// round 10
// speedup vs baseline: 2.0958x; 1.3158x over previous
#include <cuda_runtime.h>
#include <cuda_fp16.h>
#include <math.h>
#include <stdint.h>

// Problem constants (fixed by the dataset)
constexpr int cN   = 20000;
constexpr int cE   = 320000;
constexpr int cIN  = 512;
constexpr int cHID = 128;
constexpr int cH   = 8;
constexpr int cC   = 64;
constexpr int cHH  = cH * cHID;   // 1024

// ---------------------------------------------------------------------------
// Scratch (static __device__ globals; no allocation allowed)
// ---------------------------------------------------------------------------
__device__ __align__(128) float  g_ft[(size_t)cN * cHH];   // GEMM out (fp32 or fp16 alias)
__device__ __align__(128) __half g_Ah[(size_t)cN * cHH];   // A fp16
__device__ __align__(128) __half g_Bh[cHH * cHH];          // W fp16, [Nout][K]
__device__ float g_a1a[cN * cH];
__device__ float g_a2a[cN * cH];
__device__ float g_a1b[cN * cH];
__device__ float g_a2b[cN * cH];
__device__ float g_c1[3 * cH];    // per-layer, per-head logit constants
__device__ float g_c2[3 * cH];
__device__ int   g_cnt[cN];
__device__ int   g_rowptr[cN + 1];
__device__ int   g_cursor[cN];
__device__ int   g_srcsorted[cE];

// ---------------------------------------------------------------------------
// PTX helpers (base sm_80+ ISA only — harness lowers to plain sm_103)
// ---------------------------------------------------------------------------
__device__ __forceinline__ uint32_t smem_u32(const void* p) {
    uint32_t a;
    asm("{ .reg .u64 t; cvta.to.shared.u64 t, %1; cvt.u32.u64 %0, t; }" : "=r"(a) : "l"(p));
    return a;
}
__device__ __forceinline__ void cp16(uint32_t dst, const void* src, bool ok) {
    int sz = ok ? 16 : 0;
    asm volatile("cp.async.cg.shared.global [%0], [%1], 16, %2;"
                 :: "r"(dst), "l"(src), "r"(sz) : "memory");
}
__device__ __forceinline__ void cp_commit() {
    asm volatile("cp.async.commit_group;" ::: "memory");
}
__device__ __forceinline__ void mma_f16(float* d, const uint32_t* a, const uint32_t* b) {
    asm volatile(
        "mma.sync.aligned.m16n8k16.row.col.f32.f16.f16.f32 "
        "{%0,%1,%2,%3}, {%4,%5,%6,%7}, {%8,%9}, {%0,%1,%2,%3};"
        : "+f"(d[0]), "+f"(d[1]), "+f"(d[2]), "+f"(d[3])
        : "r"(a[0]), "r"(a[1]), "r"(a[2]), "r"(a[3]), "r"(b[0]), "r"(b[1]));
}
__device__ __forceinline__ void ldsm_x4(uint32_t* r, uint32_t addr) {
    asm volatile("ldmatrix.sync.aligned.m8n8.x4.shared.b16 {%0,%1,%2,%3}, [%4];"
                 : "=r"(r[0]), "=r"(r[1]), "=r"(r[2]), "=r"(r[3]) : "r"(addr));
}
__device__ __forceinline__ void ldsm_x2(uint32_t* r, uint32_t addr) {
    asm volatile("ldmatrix.sync.aligned.m8n8.x2.shared.b16 {%0,%1}, [%2];"
                 : "=r"(r[0]), "=r"(r[1]) : "r"(addr));
}

// ---------------------------------------------------------------------------
// CSR build
// ---------------------------------------------------------------------------
__global__ void zero_int_kernel(int* p, int n) {
    int i = blockIdx.x * blockDim.x + threadIdx.x;
    if (i < n) p[i] = 0;
}
__global__ void hist_kernel(const int* __restrict__ dst, int* __restrict__ cnt, int e) {
    int i = blockIdx.x * blockDim.x + threadIdx.x;
    if (i < e) atomicAdd(&cnt[dst[i]], 1);
}
__global__ void scan_kernel(const int* __restrict__ cnt, int* __restrict__ rowptr,
                            int* __restrict__ cursor, int n) {
    __shared__ int sh[1024];
    int tid = threadIdx.x;
    const int CH = (n + 1023) / 1024;
    int st = tid * CH;
    int s = 0;
    for (int i = 0; i < CH; i++) {
        int idx = st + i;
        if (idx < n) s += cnt[idx];
    }
    sh[tid] = s;
    __syncthreads();
    for (int d = 1; d < 1024; d <<= 1) {
        int v = (tid >= d) ? sh[tid - d] : 0;
        __syncthreads();
        sh[tid] += v;
        __syncthreads();
    }
    int run = sh[tid] - s;
    for (int i = 0; i < CH; i++) {
        int idx = st + i;
        if (idx < n) {
            rowptr[idx] = run;
            cursor[idx] = run;
            run += cnt[idx];
        }
    }
    if (tid == 1023) rowptr[n] = sh[1023];
}
__global__ void scatter_kernel(const int* __restrict__ src, const int* __restrict__ dst,
                               int* __restrict__ cursor, int* __restrict__ out, int e) {
    int i = blockIdx.x * blockDim.x + threadIdx.x;
    if (i < e) {
        int d = dst[i];
        int pos = atomicAdd(&cursor[d], 1);
        out[pos] = src[i];
    }
}

// ---------------------------------------------------------------------------
// fp32 -> fp16 convert (first-layer features), float4 vectorized
// ---------------------------------------------------------------------------
__global__ void tohalf_kernel(const float* __restrict__ in,
                              __half* __restrict__ out, int n4) {
    int i = blockIdx.x * blockDim.x + threadIdx.x;
    if (i >= n4) return;
    float4 v = ((const float4*)in)[i];
    ((__half2*)out)[i * 2]     = __floats2half2_rn(v.x, v.y);
    ((__half2*)out)[i * 2 + 1] = __floats2half2_rn(v.z, v.w);
}

// ---------------------------------------------------------------------------
// Weight prep via SMEM tile transpose (coalesced both sides):
// W [h][k][j] (j contiguous) -> B [n = h*HIDo + j][k] fp16
// ---------------------------------------------------------------------------
__global__ void wprep_t_kernel(const float* __restrict__ W,
                               __half* __restrict__ Bh, int K, int HIDo) {
    __shared__ __half tile[32][33];
    int h  = blockIdx.z;
    int k0 = blockIdx.x * 32;
    int j0 = blockIdx.y * 32;
    const float* Wp = W + (size_t)h * K * HIDo;
    int tx = threadIdx.x, ty = threadIdx.y;
#pragma unroll
    for (int i = 0; i < 32; i += 8)
        tile[ty + i][tx] = __float2half_rn(Wp[(size_t)(k0 + ty + i) * HIDo + j0 + tx]);
    __syncthreads();
#pragma unroll
    for (int i = 0; i < 32; i += 8)
        Bh[(size_t)(h * HIDo + j0 + ty + i) * K + k0 + tx] = tile[tx][ty + i];
}

// ---------------------------------------------------------------------------
// Per-head logit constants: c1[h] = alb[h] + dot(bias_head, al_head)
// ---------------------------------------------------------------------------
__global__ void logit_const_kernel(const float* __restrict__ bias,
                                   const float* __restrict__ al,
                                   const float* __restrict__ alb,
                                   const float* __restrict__ ar,
                                   const float* __restrict__ arb,
                                   float* __restrict__ c1, float* __restrict__ c2,
                                   int Hn, int HIDo) {
    int h = threadIdx.x >> 5;
    int lane = threadIdx.x & 31;
    if (h >= Hn) return;
    float s1 = 0.f, s2 = 0.f;
    for (int j = lane; j < HIDo; j += 32) {
        float b = bias[h * HIDo + j];
        s1 = fmaf(b, al[h * HIDo + j], s1);
        s2 = fmaf(b, ar[h * HIDo + j], s2);
    }
    for (int o = 16; o; o >>= 1) {
        s1 += __shfl_xor_sync(0xffffffffu, s1, o);
        s2 += __shfl_xor_sync(0xffffffffu, s2, o);
    }
    if (lane == 0) {
        c1[h] = s1 + alb[h];
        c2[h] = s2 + arb[h];
    }
}

__global__ void logit_init_kernel(const float* __restrict__ c1,
                                  const float* __restrict__ c2,
                                  float* __restrict__ a1, float* __restrict__ a2,
                                  int total, int Hn) {
    int i = blockIdx.x * blockDim.x + threadIdx.x;
    if (i >= total) return;
    int h = i % Hn;
    a1[i] = c1[h];
    a2[i] = c2[h];
}

// ---------------------------------------------------------------------------
// fp16 warp-MMA GEMM with fused bias + fused attention-logit dots.
//   C(fp32 acc) = A(fp16) @ W(fp16)^T
// Fragments via ldmatrix (x4 A, x2 B); 80B padded rows conflict-free.
// Tile: BM=128 x BN x BK=32, 8 warps (2x4), 3-stage cp.async pipeline.
// HALFOUT: write C as fp16 (feeds fp16-gather aggregate).
// Epilogue: bias add + C store + per-row a1/a2 partial dots -> atomicAdd.
// ---------------------------------------------------------------------------
template<int BN, bool HALFOUT>
__global__ __launch_bounds__(256, 2)
void gemm_mma_kernel(const __half* __restrict__ Ah,
                     const __half* __restrict__ Bh,
                     const float* __restrict__ bias,
                     const float* __restrict__ al,
                     const float* __restrict__ ar,
                     float* __restrict__ a1g,
                     float* __restrict__ a2g,
                     void* __restrict__ Cv,
                     int M, int K, int ldc, int Hn) {
    constexpr int MT  = 4;          // m16 tiles per warp (64 rows)
    constexpr int WNC = BN / 4;     // cols per warp
    constexpr int NTL = WNC / 8;    // n8 tiles per warp
    constexpr int ASZ = 128 * 80;   // bytes, one A operand tile (padded rows)
    constexpr int BSZ = BN * 80;
    constexpr int STAGE = ASZ + BSZ;

    extern __shared__ char smem[];
    const uint32_t sbase = smem_u32(smem);

    const int tid = threadIdx.x;
    const int wid = tid >> 5;
    const int lid = tid & 31;
    const int wr = wid >> 2;        // 0..1
    const int wc = wid & 3;         // 0..3
    const int g  = lid >> 2;
    const int t  = lid & 3;

    const int row0 = blockIdx.y * 128;
    const int col0 = blockIdx.x * BN;
    const int h    = blockIdx.x;    // head index (BN == head dim)

    // ldmatrix per-lane in-tile offsets
    const int lr = lid & 7;
    const uint32_t aOff = (uint32_t)(wr * 64 + ((lid >> 3) & 1) * 8 + lr) * 80
                        + (uint32_t)(lid >> 4) * 16;
    const uint32_t bOff = (uint32_t)(wc * WNC + lr) * 80
                        + (uint32_t)((lid >> 3) & 1) * 16;

    float acc[MT][NTL][4];
#pragma unroll
    for (int m = 0; m < MT; m++)
#pragma unroll
        for (int n = 0; n < NTL; n++)
#pragma unroll
            for (int q = 0; q < 4; q++) acc[m][n][q] = 0.f;

    const int nch = K >> 5;

    auto ld_stage = [&](int s, int k0) {
        const uint32_t sb = sbase + s * STAGE;
#pragma unroll
        for (int c = tid; c < 512; c += 256) {
            int r = c >> 2, q = c & 3;
            int gr = row0 + r;
            bool ok = gr < M;
            size_t goff = (size_t)(ok ? gr : row0) * K + k0 + q * 8;
            cp16(sb + r * 80 + q * 16, Ah + goff, ok);
        }
#pragma unroll
        for (int c = tid; c < BN * 4; c += 256) {
            int r = c >> 2, q = c & 3;
            size_t goff = (size_t)(col0 + r) * K + k0 + q * 8;
            cp16(sb + ASZ + r * 80 + q * 16, Bh + goff, true);
        }
    };

    ld_stage(0, 0);
    cp_commit();
    ld_stage(1, 32);
    cp_commit();

    for (int i = 0; i < nch; i++) {
        if (i + 2 < nch) {
            ld_stage((i + 2) % 3, (i + 2) * 32);
            cp_commit();
            asm volatile("cp.async.wait_group 2;" ::: "memory");
        } else if (i + 1 < nch) {
            asm volatile("cp.async.wait_group 1;" ::: "memory");
        } else {
            asm volatile("cp.async.wait_group 0;" ::: "memory");
        }
        __syncthreads();

        const uint32_t sA = sbase + (i % 3) * STAGE;
        const uint32_t sB = sA + ASZ;

#pragma unroll
        for (int ks = 0; ks < 2; ks++) {
            const uint32_t kcol = ks * 32;

            uint32_t bf[NTL][2];
#pragma unroll
            for (int n = 0; n < NTL; n++)
                ldsm_x2(bf[n], sB + bOff + n * (8 * 80) + kcol);
#pragma unroll
            for (int m = 0; m < MT; m++) {
                uint32_t af[4];
                ldsm_x4(af, sA + aOff + m * (16 * 80) + kcol);
#pragma unroll
                for (int n = 0; n < NTL; n++)
                    mma_f16(acc[m][n], af, bf[n]);
            }
        }
        __syncthreads();
    }

    // ---- Epilogue: bias add + C store + fused logit partial dots ----
    float alv[NTL][2], arv[NTL][2], bv[NTL][2];
#pragma unroll
    for (int n = 0; n < NTL; n++) {
        int cc = col0 + wc * WNC + n * 8 + t * 2;
        alv[n][0] = al[cc]; alv[n][1] = al[cc + 1];
        arv[n][0] = ar[cc]; arv[n][1] = ar[cc + 1];
        bv[n][0]  = bias[cc]; bv[n][1] = bias[cc + 1];
    }

#pragma unroll
    for (int m = 0; m < MT; m++) {
        int r0r = row0 + wr * 64 + m * 16 + g;
        int r1r = r0r + 8;
        float p1a = 0.f, p2a = 0.f, p1b = 0.f, p2b = 0.f;
#pragma unroll
        for (int n = 0; n < NTL; n++) {
            float c0 = acc[m][n][0] + bv[n][0];
            float c1 = acc[m][n][1] + bv[n][1];
            float c2 = acc[m][n][2] + bv[n][0];
            float c3 = acc[m][n][3] + bv[n][1];
            int cc = col0 + wc * WNC + n * 8 + t * 2;
            if (HALFOUT) {
                __half* Ch = (__half*)Cv;
                if (r0r < M)
                    *(__half2*)(Ch + (size_t)r0r * ldc + cc) = __floats2half2_rn(c0, c1);
                if (r1r < M)
                    *(__half2*)(Ch + (size_t)r1r * ldc + cc) = __floats2half2_rn(c2, c3);
            } else {
                float* Cf = (float*)Cv;
                if (r0r < M)
                    *(float2*)(Cf + (size_t)r0r * ldc + cc) = make_float2(c0, c1);
                if (r1r < M)
                    *(float2*)(Cf + (size_t)r1r * ldc + cc) = make_float2(c2, c3);
            }
            p1a = fmaf(c0, alv[n][0], fmaf(c1, alv[n][1], p1a));
            p2a = fmaf(c0, arv[n][0], fmaf(c1, arv[n][1], p2a));
            p1b = fmaf(c2, alv[n][0], fmaf(c3, alv[n][1], p1b));
            p2b = fmaf(c2, arv[n][0], fmaf(c3, arv[n][1], p2b));
        }
#pragma unroll
        for (int o = 1; o <= 2; o <<= 1) {
            p1a += __shfl_xor_sync(0xffffffffu, p1a, o);
            p2a += __shfl_xor_sync(0xffffffffu, p2a, o);
            p1b += __shfl_xor_sync(0xffffffffu, p1b, o);
            p2b += __shfl_xor_sync(0xffffffffu, p2b, o);
        }
        if (t == 0) {
            if (r0r < M) {
                atomicAdd(&a1g[r0r * Hn + h], p1a);
                atomicAdd(&a2g[r0r * Hn + h], p2a);
            }
            if (r1r < M) {
                atomicAdd(&a1g[r1r * Hn + h], p1b);
                atomicAdd(&a2g[r1r * Hn + h], p2b);
            }
        }
    }
}

// ---------------------------------------------------------------------------
// Edge-softmax + aggregation + ELU — single-pass ONLINE softmax.
// One warp per (node, head). HALFIN: gather fp16 ft.
// HALFSTORE: write fp16 output (feeds next GEMM); else fp32 out.
// Also initializes NEXT layer's a1/a2 buffers (double-buffered, race-free).
// ---------------------------------------------------------------------------
template<int VEC, bool HALFIN, bool HALFSTORE>
__global__ void aggregate_kernel(const void* __restrict__ ftv,
                                 const float* __restrict__ a1,
                                 const float* __restrict__ a2,
                                 const int* __restrict__ rowptr,
                                 const int* __restrict__ srcs,
                                 float* __restrict__ out,
                                 __half* __restrict__ outH,
                                 const float* __restrict__ c1n,
                                 const float* __restrict__ c2n,
                                 float* __restrict__ a1n,
                                 float* __restrict__ a2n,
                                 int HnNext,
                                 int Nn, int Hn, int ld) {
    constexpr int HIDo = VEC * 32;
    int gw   = (blockIdx.x * blockDim.x + threadIdx.x) >> 5;
    int lane = threadIdx.x & 31;
    if (gw >= Nn * Hn) return;
    int n = gw / Hn;
    int h = gw - n * Hn;
    int beg = rowptr[n];
    int end = rowptr[n + 1];
    float a1v = a1[n * Hn + h];

    float m = -1e30f, den = 0.f;
    float acc[VEC];
#pragma unroll
    for (int r = 0; r < VEC; r++) acc[r] = 0.f;

    for (int e0 = beg; e0 < end; e0 += 32) {
        int e = e0 + lane;
        float s = -1e30f;
        int sv = 0;
        if (e < end) {
            sv = srcs[e];
            float x = a1v + a2[sv * Hn + h];
            s = (x >= 0.f) ? x : 0.01f * x;
        }
        float bm = s;
        for (int o = 16; o; o >>= 1) bm = fmaxf(bm, __shfl_xor_sync(0xffffffffu, bm, o));
        float nm = fmaxf(m, bm);
        float scale = __expf(m - nm);
        den *= scale;
#pragma unroll
        for (int r = 0; r < VEC; r++) acc[r] *= scale;
        m = nm;

        float ev = __expf(s - nm);
        den += ev;

        int cnt = min(32, end - e0);
        for (int i = 0; i < cnt; i++) {
            float wi = __shfl_sync(0xffffffffu, ev, i);
            int   si = __shfl_sync(0xffffffffu, sv, i);
            if constexpr (HALFIN) {
                const __half* fp = (const __half*)ftv + (size_t)si * ld + h * HIDo;
                if (VEC == 4) {
                    uint2 raw = *((const uint2*)fp + lane);
                    float2 v01 = __half22float2(*reinterpret_cast<__half2*>(&raw.x));
                    float2 v23 = __half22float2(*reinterpret_cast<__half2*>(&raw.y));
                    acc[0] = fmaf(wi, v01.x, acc[0]);
                    acc[1] = fmaf(wi, v01.y, acc[1]);
                    acc[2] = fmaf(wi, v23.x, acc[2]);
                    acc[3] = fmaf(wi, v23.y, acc[3]);
                } else {
                    uint32_t raw = *((const uint32_t*)fp + lane);
                    float2 v01 = __half22float2(*reinterpret_cast<__half2*>(&raw));
                    acc[0] = fmaf(wi, v01.x, acc[0]);
                    acc[1] = fmaf(wi, v01.y, acc[1]);
                }
            } else {
                const float* fp = (const float*)ftv + (size_t)si * ld + h * HIDo;
                if (VEC == 4) {
                    float4 v = *((const float4*)fp + lane);
                    acc[0] = fmaf(wi, v.x, acc[0]);
                    acc[1] = fmaf(wi, v.y, acc[1]);
                    acc[2] = fmaf(wi, v.z, acc[2]);
                    acc[3] = fmaf(wi, v.w, acc[3]);
                } else {
                    float2 v = *((const float2*)fp + lane);
                    acc[0] = fmaf(wi, v.x, acc[0]);
                    acc[1] = fmaf(wi, v.y, acc[1]);
                }
            }
        }
    }
    for (int o = 16; o; o >>= 1) den += __shfl_xor_sync(0xffffffffu, den, o);
    float inv = 1.f / den;

    float r[VEC];
#pragma unroll
    for (int q = 0; q < VEC; q++) {
        float v = acc[q] * inv;
        r[q] = (v > 0.f) ? v : expm1f(v);
    }

    size_t ob = (size_t)n * ld + h * HIDo + lane * VEC;
    if constexpr (HALFSTORE) {
        if (VEC == 4) {
            *(__half2*)(outH + ob)     = __floats2half2_rn(r[0], r[1]);
            *(__half2*)(outH + ob + 2) = __floats2half2_rn(r[2], r[3]);
        } else {
            *(__half2*)(outH + ob) = __floats2half2_rn(r[0], r[1]);
        }
    } else {
        if (VEC == 4) {
            *(float4*)(out + ob) = make_float4(r[0], r[1], r[2], r[3]);
        } else {
            *(float2*)(out + ob) = make_float2(r[0], r[1]);
        }
    }

    // fused init of the NEXT layer's logit buffers (double-buffered, no race)
    if (a1n != nullptr && lane == 0 && h < HnNext) {
        a1n[n * HnNext + h] = c1n[h];
        a2n[n * HnNext + h] = c2n[h];
    }
}

// ---------------------------------------------------------------------------
// Host launch
// ---------------------------------------------------------------------------
extern "C" void kernel_launch(void* const* d_in, const int* in_sizes, int n_in,
                              void* d_out, int out_size) {
    const float* features = (const float*)d_in[0];
    const int*   src      = (const int*)d_in[1];
    const int*   dst      = (const int*)d_in[2];
    const float* W0  = (const float*)d_in[3];
    const float* b0  = (const float*)d_in[4];
    const float* al0 = (const float*)d_in[5];
    const float* alb0= (const float*)d_in[6];
    const float* ar0 = (const float*)d_in[7];
    const float* arb0= (const float*)d_in[8];
    const float* W1  = (const float*)d_in[9];
    const float* b1  = (const float*)d_in[10];
    const float* al1 = (const float*)d_in[11];
    const float* alb1= (const float*)d_in[12];
    const float* ar1 = (const float*)d_in[13];
    const float* arb1= (const float*)d_in[14];
    const float* Wf  = (const float*)d_in[15];
    const float* bfv = (const float*)d_in[16];
    const float* alf = (const float*)d_in[17];
    const float* albf= (const float*)d_in[18];
    const float* arf = (const float*)d_in[19];
    const float* arbf= (const float*)d_in[20];

    float *ft, *a1a, *a2a, *a1b, *a2b, *c1, *c2;
    __half *Ah, *Bh;
    int *cnt, *rowptr, *cursor, *ssrc;
    cudaGetSymbolAddress((void**)&ft,  g_ft);
    cudaGetSymbolAddress((void**)&Ah,  g_Ah);
    cudaGetSymbolAddress((void**)&Bh,  g_Bh);
    cudaGetSymbolAddress((void**)&a1a, g_a1a);
    cudaGetSymbolAddress((void**)&a2a, g_a2a);
    cudaGetSymbolAddress((void**)&a1b, g_a1b);
    cudaGetSymbolAddress((void**)&a2b, g_a2b);
    cudaGetSymbolAddress((void**)&c1, g_c1);
    cudaGetSymbolAddress((void**)&c2, g_c2);
    cudaGetSymbolAddress((void**)&cnt, g_cnt);
    cudaGetSymbolAddress((void**)&rowptr, g_rowptr);
    cudaGetSymbolAddress((void**)&cursor, g_cursor);
    cudaGetSymbolAddress((void**)&ssrc, g_srcsorted);

    __half* fth = (__half*)ft;   // fp16 alias of the ft buffer (mid layers)

    // SMEM: 3 stages * (A(128*80) + B(BN*80))
    constexpr int SMEM128 = 3 * (128 * 80 + 128 * 80);  // 61440
    constexpr int SMEM64  = 3 * (128 * 80 + 64 * 80);   // 46080
    cudaFuncSetAttribute(gemm_mma_kernel<128, true>,
                         cudaFuncAttributeMaxDynamicSharedMemorySize, SMEM128);
    cudaFuncSetAttribute(gemm_mma_kernel<64, false>,
                         cudaFuncAttributeMaxDynamicSharedMemorySize, SMEM64);

    // --- CSR build ---
    zero_int_kernel<<<(cN + 255) / 256, 256>>>(cnt, cN);
    hist_kernel<<<(cE + 255) / 256, 256>>>(dst, cnt, cE);
    scan_kernel<<<1, 1024>>>(cnt, rowptr, cursor, cN);
    scatter_kernel<<<(cE + 255) / 256, 256>>>(src, dst, cursor, ssrc, cE);

    const int gridM = (cN + 127) / 128;   // 157
    const int warpBlocksH = (cN * cH * 32 + 255) / 256;
    const int warpBlocks1 = (cN * 32 + 255) / 256;

    // --- logit constants for all 3 layers ---
    logit_const_kernel<<<1, 256>>>(b0, al0, alb0, ar0, arb0, c1, c2, cH, cHID);
    logit_const_kernel<<<1, 256>>>(b1, al1, alb1, ar1, arb1, c1 + cH, c2 + cH, cH, cHID);
    logit_const_kernel<<<1, 32>>>(bfv, alf, albf, arf, arbf, c1 + 2 * cH, c2 + 2 * cH, 1, cC);

    // --- layer 0 ---
    tohalf_kernel<<<(cN * cIN / 4 + 255) / 256, 256>>>(features, Ah, cN * cIN / 4);
    wprep_t_kernel<<<dim3(cIN / 32, cHID / 32, cH), dim3(32, 8)>>>(W0, Bh, cIN, cHID);
    logit_init_kernel<<<(cN * cH + 255) / 256, 256>>>(c1, c2, a1a, a2a, cN * cH, cH);
    gemm_mma_kernel<128, true><<<dim3(8, gridM), 256, SMEM128>>>(
        Ah, Bh, b0, al0, ar0, a1a, a2a, fth, cN, cIN, cHH, cH);
    aggregate_kernel<4, true, true><<<warpBlocksH, 256>>>(
        fth, a1a, a2a, rowptr, ssrc, nullptr, Ah,
        c1 + cH, c2 + cH, a1b, a2b, cH, cN, cH, cHH);

    // --- layer 1 ---
    wprep_t_kernel<<<dim3(cHH / 32, cHID / 32, cH), dim3(32, 8)>>>(W1, Bh, cHH, cHID);
    gemm_mma_kernel<128, true><<<dim3(8, gridM), 256, SMEM128>>>(
        Ah, Bh, b1, al1, ar1, a1b, a2b, fth, cN, cHH, cHH, cH);
    aggregate_kernel<4, true, true><<<warpBlocksH, 256>>>(
        fth, a1b, a2b, rowptr, ssrc, nullptr, Ah,
        c1 + 2 * cH, c2 + 2 * cH, a1a, a2a, 1, cN, cH, cHH);

    // --- final layer ---
    wprep_t_kernel<<<dim3(cHH / 32, cC / 32, 1), dim3(32, 8)>>>(Wf, Bh, cHH, cC);
    gemm_mma_kernel<64, false><<<dim3(1, gridM), 256, SMEM64>>>(
        Ah, Bh, bfv, alf, arf, a1a, a2a, ft, cN, cHH, cC, 1);
    aggregate_kernel<2, false, false><<<warpBlocks1, 256>>>(
        ft, a1a, a2a, rowptr, ssrc, (float*)d_out, nullptr,
        nullptr, nullptr, nullptr, nullptr, 0, cN, 1, cC);
}

// round 11
// speedup vs baseline: 2.2272x; 1.0627x over previous
#include <cuda_runtime.h>
#include <cuda_fp16.h>
#include <math.h>
#include <stdint.h>

// Problem constants (fixed by the dataset)
constexpr int cN   = 20000;
constexpr int cE   = 320000;
constexpr int cIN  = 512;
constexpr int cHID = 128;
constexpr int cH   = 8;
constexpr int cC   = 64;
constexpr int cHH  = cH * cHID;   // 1024

// ---------------------------------------------------------------------------
// Scratch (static __device__ globals; no allocation allowed)
// ---------------------------------------------------------------------------
__device__ __align__(128) float  g_ft[(size_t)cN * cHH];   // GEMM out (fp32 or fp16 alias)
__device__ __align__(128) __half g_Ah[(size_t)cN * cHH];   // A fp16
__device__ __align__(128) __half g_Bh[cHH * cHH];          // W fp16, [Nout][K]
__device__ float g_a1[cN * cH];
__device__ float g_a2[cN * cH];
__device__ float g_c1[3 * cH];    // per-layer, per-head logit constants
__device__ float g_c2[3 * cH];
__device__ int   g_cnt[cN];
__device__ int   g_rowptr[cN + 1];
__device__ int   g_cursor[cN];
__device__ int   g_srcsorted[cE];

// ---------------------------------------------------------------------------
// PTX helpers (base sm_80+ ISA only — harness lowers to plain sm_103)
// ---------------------------------------------------------------------------
__device__ __forceinline__ uint32_t smem_u32(const void* p) {
    uint32_t a;
    asm("{ .reg .u64 t; cvta.to.shared.u64 t, %1; cvt.u32.u64 %0, t; }" : "=r"(a) : "l"(p));
    return a;
}
__device__ __forceinline__ void cp16(uint32_t dst, const void* src, bool ok) {
    int sz = ok ? 16 : 0;
    asm volatile("cp.async.cg.shared.global [%0], [%1], 16, %2;"
                 :: "r"(dst), "l"(src), "r"(sz) : "memory");
}
__device__ __forceinline__ void cp_commit() {
    asm volatile("cp.async.commit_group;" ::: "memory");
}
__device__ __forceinline__ void mma_f16(float* d, const uint32_t* a, const uint32_t* b) {
    asm volatile(
        "mma.sync.aligned.m16n8k16.row.col.f32.f16.f16.f32 "
        "{%0,%1,%2,%3}, {%4,%5,%6,%7}, {%8,%9}, {%0,%1,%2,%3};"
        : "+f"(d[0]), "+f"(d[1]), "+f"(d[2]), "+f"(d[3])
        : "r"(a[0]), "r"(a[1]), "r"(a[2]), "r"(a[3]), "r"(b[0]), "r"(b[1]));
}
__device__ __forceinline__ void ldsm_x4(uint32_t* r, uint32_t addr) {
    asm volatile("ldmatrix.sync.aligned.m8n8.x4.shared.b16 {%0,%1,%2,%3}, [%4];"
                 : "=r"(r[0]), "=r"(r[1]), "=r"(r[2]), "=r"(r[3]) : "r"(addr));
}
__device__ __forceinline__ void ldsm_x2(uint32_t* r, uint32_t addr) {
    asm volatile("ldmatrix.sync.aligned.m8n8.x2.shared.b16 {%0,%1}, [%2];"
                 : "=r"(r[0]), "=r"(r[1]) : "r"(addr));
}

// ---------------------------------------------------------------------------
// CSR build
// ---------------------------------------------------------------------------
__global__ void zero_int_kernel(int* p, int n) {
    int i = blockIdx.x * blockDim.x + threadIdx.x;
    if (i < n) p[i] = 0;
}
__global__ void hist_kernel(const int* __restrict__ dst, int* __restrict__ cnt, int e) {
    int i = blockIdx.x * blockDim.x + threadIdx.x;
    if (i < e) atomicAdd(&cnt[dst[i]], 1);
}
__global__ void scan_kernel(const int* __restrict__ cnt, int* __restrict__ rowptr,
                            int* __restrict__ cursor, int n) {
    __shared__ int sh[1024];
    int tid = threadIdx.x;
    const int CH = (n + 1023) / 1024;
    int st = tid * CH;
    int s = 0;
    for (int i = 0; i < CH; i++) {
        int idx = st + i;
        if (idx < n) s += cnt[idx];
    }
    sh[tid] = s;
    __syncthreads();
    for (int d = 1; d < 1024; d <<= 1) {
        int v = (tid >= d) ? sh[tid - d] : 0;
        __syncthreads();
        sh[tid] += v;
        __syncthreads();
    }
    int run = sh[tid] - s;
    for (int i = 0; i < CH; i++) {
        int idx = st + i;
        if (idx < n) {
            rowptr[idx] = run;
            cursor[idx] = run;
            run += cnt[idx];
        }
    }
    if (tid == 1023) rowptr[n] = sh[1023];
}
__global__ void scatter_kernel(const int* __restrict__ src, const int* __restrict__ dst,
                               int* __restrict__ cursor, int* __restrict__ out, int e) {
    int i = blockIdx.x * blockDim.x + threadIdx.x;
    if (i < e) {
        int d = dst[i];
        int pos = atomicAdd(&cursor[d], 1);
        out[pos] = src[i];
    }
}

// ---------------------------------------------------------------------------
// fp32 -> fp16 convert (first-layer features), float4 vectorized
// ---------------------------------------------------------------------------
__global__ void tohalf_kernel(const float* __restrict__ in,
                              __half* __restrict__ out, int n4) {
    int i = blockIdx.x * blockDim.x + threadIdx.x;
    if (i >= n4) return;
    float4 v = ((const float4*)in)[i];
    ((__half2*)out)[i * 2]     = __floats2half2_rn(v.x, v.y);
    ((__half2*)out)[i * 2 + 1] = __floats2half2_rn(v.z, v.w);
}

// ---------------------------------------------------------------------------
// Weight prep via SMEM tile transpose (coalesced both sides):
// W [h][k][j] (j contiguous) -> B [n = h*HIDo + j][k] fp16
// ---------------------------------------------------------------------------
__global__ void wprep_t_kernel(const float* __restrict__ W,
                               __half* __restrict__ Bh, int K, int HIDo) {
    __shared__ __half tile[32][33];
    int h  = blockIdx.z;
    int k0 = blockIdx.x * 32;
    int j0 = blockIdx.y * 32;
    const float* Wp = W + (size_t)h * K * HIDo;
    int tx = threadIdx.x, ty = threadIdx.y;
#pragma unroll
    for (int i = 0; i < 32; i += 8)
        tile[ty + i][tx] = __float2half_rn(Wp[(size_t)(k0 + ty + i) * HIDo + j0 + tx]);
    __syncthreads();
#pragma unroll
    for (int i = 0; i < 32; i += 8)
        Bh[(size_t)(h * HIDo + j0 + ty + i) * K + k0 + tx] = tile[tx][ty + i];
}

// ---------------------------------------------------------------------------
// Per-head logit constants: c1[h] = alb[h] + dot(bias_head, al_head)
// ---------------------------------------------------------------------------
__global__ void logit_const_kernel(const float* __restrict__ bias,
                                   const float* __restrict__ al,
                                   const float* __restrict__ alb,
                                   const float* __restrict__ ar,
                                   const float* __restrict__ arb,
                                   float* __restrict__ c1, float* __restrict__ c2,
                                   int Hn, int HIDo) {
    int h = threadIdx.x >> 5;
    int lane = threadIdx.x & 31;
    if (h >= Hn) return;
    float s1 = 0.f, s2 = 0.f;
    for (int j = lane; j < HIDo; j += 32) {
        float b = bias[h * HIDo + j];
        s1 = fmaf(b, al[h * HIDo + j], s1);
        s2 = fmaf(b, ar[h * HIDo + j], s2);
    }
    for (int o = 16; o; o >>= 1) {
        s1 += __shfl_xor_sync(0xffffffffu, s1, o);
        s2 += __shfl_xor_sync(0xffffffffu, s2, o);
    }
    if (lane == 0) {
        c1[h] = s1 + alb[h];
        c2[h] = s2 + arb[h];
    }
}

// ---------------------------------------------------------------------------
// Persistent fp16 warp-MMA GEMM, fused bias + COMPLETE attention-logit write.
//   C(fp32 acc) = A(fp16) @ W(fp16)^T
// Grid = min(nTiles, 296) persistent CTAs looping over tiles (col fastest ->
// concurrent CTAs share the A row panel in L2; no wave-quantization tail).
// Exactly ONE CTA owns each (row, head): per-tile SMEM reduction over the 4
// column-warps, then plain stores  a1 = c1[h] + dot(C_row, al_head)  (no
// global atomics, no separate logit-init pass).
// HALFOUT: write C as fp16 (feeds fp16-gather aggregate).
// ---------------------------------------------------------------------------
template<int BN, bool HALFOUT>
__global__ __launch_bounds__(256, 2)
void gemm_mma_kernel(const __half* __restrict__ Ah,
                     const __half* __restrict__ Bh,
                     const float* __restrict__ bias,
                     const float* __restrict__ al,
                     const float* __restrict__ ar,
                     const float* __restrict__ c1,
                     const float* __restrict__ c2,
                     float* __restrict__ a1g,
                     float* __restrict__ a2g,
                     void* __restrict__ Cv,
                     int M, int K, int ldc, int Hn, int nTiles) {
    constexpr int MT  = 4;          // m16 tiles per warp (64 rows)
    constexpr int WNC = BN / 4;     // cols per warp
    constexpr int NTL = WNC / 8;    // n8 tiles per warp
    constexpr int ASZ = 128 * 80;   // bytes, one A operand tile (padded rows)
    constexpr int BSZ = BN * 80;
    constexpr int STAGE = ASZ + BSZ;

    extern __shared__ char smem[];
    const uint32_t sbase = smem_u32(smem);
    float* sred = (float*)(smem + 3 * STAGE);   // [256]: p1[128], p2[128]

    const int tid = threadIdx.x;
    const int wid = tid >> 5;
    const int lid = tid & 31;
    const int wr = wid >> 2;        // 0..1
    const int wc = wid & 3;         // 0..3
    const int g  = lid >> 2;
    const int t  = lid & 3;

    // ldmatrix per-lane in-tile offsets
    const int lr = lid & 7;
    const uint32_t aOff = (uint32_t)(wr * 64 + ((lid >> 3) & 1) * 8 + lr) * 80
                        + (uint32_t)(lid >> 4) * 16;
    const uint32_t bOff = (uint32_t)(wc * WNC + lr) * 80
                        + (uint32_t)((lid >> 3) & 1) * 16;

    const int nch = K >> 5;

    for (int tile = blockIdx.x; tile < nTiles; tile += gridDim.x) {
        const int h    = tile % Hn;          // col block == head (BN == head dim)
        const int rowb = tile / Hn;
        const int row0 = rowb * 128;
        const int col0 = h * BN;

        float acc[MT][NTL][4];
#pragma unroll
        for (int m = 0; m < MT; m++)
#pragma unroll
            for (int n = 0; n < NTL; n++)
#pragma unroll
                for (int q = 0; q < 4; q++) acc[m][n][q] = 0.f;

        // zero logit-reduction buffer
        if (tid < 128) { sred[tid] = 0.f; sred[128 + tid] = 0.f; }

        auto ld_stage = [&](int s, int k0) {
            const uint32_t sb = sbase + s * STAGE;
#pragma unroll
            for (int c = tid; c < 512; c += 256) {
                int r = c >> 2, q = c & 3;
                int gr = row0 + r;
                bool ok = gr < M;
                size_t goff = (size_t)(ok ? gr : row0) * K + k0 + q * 8;
                cp16(sb + r * 80 + q * 16, Ah + goff, ok);
            }
#pragma unroll
            for (int c = tid; c < BN * 4; c += 256) {
                int r = c >> 2, q = c & 3;
                size_t goff = (size_t)(col0 + r) * K + k0 + q * 8;
                cp16(sb + ASZ + r * 80 + q * 16, Bh + goff, true);
            }
        };

        ld_stage(0, 0);
        cp_commit();
        ld_stage(1, 32);
        cp_commit();

        for (int i = 0; i < nch; i++) {
            if (i + 2 < nch) {
                ld_stage((i + 2) % 3, (i + 2) * 32);
                cp_commit();
                asm volatile("cp.async.wait_group 2;" ::: "memory");
            } else if (i + 1 < nch) {
                asm volatile("cp.async.wait_group 1;" ::: "memory");
            } else {
                asm volatile("cp.async.wait_group 0;" ::: "memory");
            }
            __syncthreads();

            const uint32_t sA = sbase + (i % 3) * STAGE;
            const uint32_t sB = sA + ASZ;

#pragma unroll
            for (int ks = 0; ks < 2; ks++) {
                const uint32_t kcol = ks * 32;

                uint32_t bf[NTL][2];
#pragma unroll
                for (int n = 0; n < NTL; n++)
                    ldsm_x2(bf[n], sB + bOff + n * (8 * 80) + kcol);
#pragma unroll
                for (int m = 0; m < MT; m++) {
                    uint32_t af[4];
                    ldsm_x4(af, sA + aOff + m * (16 * 80) + kcol);
#pragma unroll
                    for (int n = 0; n < NTL; n++)
                        mma_f16(acc[m][n], af, bf[n]);
                }
            }
            __syncthreads();
        }

        // ---- Epilogue: bias add + C store + logit partials -> SMEM ----
        float alv[NTL][2], arv[NTL][2], bv[NTL][2];
#pragma unroll
        for (int n = 0; n < NTL; n++) {
            int cc = col0 + wc * WNC + n * 8 + t * 2;
            alv[n][0] = al[cc]; alv[n][1] = al[cc + 1];
            arv[n][0] = ar[cc]; arv[n][1] = ar[cc + 1];
            bv[n][0]  = bias[cc]; bv[n][1] = bias[cc + 1];
        }

#pragma unroll
        for (int m = 0; m < MT; m++) {
            int rl0 = wr * 64 + m * 16 + g;     // local row
            int rl1 = rl0 + 8;
            int r0r = row0 + rl0;
            int r1r = row0 + rl1;
            float p1a = 0.f, p2a = 0.f, p1b = 0.f, p2b = 0.f;
#pragma unroll
            for (int n = 0; n < NTL; n++) {
                float c0 = acc[m][n][0] + bv[n][0];
                float c1v_ = acc[m][n][1] + bv[n][1];
                float c2v_ = acc[m][n][2] + bv[n][0];
                float c3 = acc[m][n][3] + bv[n][1];
                int cc = col0 + wc * WNC + n * 8 + t * 2;
                if (HALFOUT) {
                    __half* Ch = (__half*)Cv;
                    if (r0r < M)
                        *(__half2*)(Ch + (size_t)r0r * ldc + cc) = __floats2half2_rn(c0, c1v_);
                    if (r1r < M)
                        *(__half2*)(Ch + (size_t)r1r * ldc + cc) = __floats2half2_rn(c2v_, c3);
                } else {
                    float* Cf = (float*)Cv;
                    if (r0r < M)
                        *(float2*)(Cf + (size_t)r0r * ldc + cc) = make_float2(c0, c1v_);
                    if (r1r < M)
                        *(float2*)(Cf + (size_t)r1r * ldc + cc) = make_float2(c2v_, c3);
                }
                p1a = fmaf(c0, alv[n][0], fmaf(c1v_, alv[n][1], p1a));
                p2a = fmaf(c0, arv[n][0], fmaf(c1v_, arv[n][1], p2a));
                p1b = fmaf(c2v_, alv[n][0], fmaf(c3, alv[n][1], p1b));
                p2b = fmaf(c2v_, arv[n][0], fmaf(c3, arv[n][1], p2b));
            }
#pragma unroll
            for (int o = 1; o <= 2; o <<= 1) {
                p1a += __shfl_xor_sync(0xffffffffu, p1a, o);
                p2a += __shfl_xor_sync(0xffffffffu, p2a, o);
                p1b += __shfl_xor_sync(0xffffffffu, p1b, o);
                p2b += __shfl_xor_sync(0xffffffffu, p2b, o);
            }
            if (t == 0) {
                atomicAdd(&sred[rl0], p1a);
                atomicAdd(&sred[128 + rl0], p2a);
                atomicAdd(&sred[rl1], p1b);
                atomicAdd(&sred[128 + rl1], p2b);
            }
        }
        __syncthreads();
        if (tid < 128) {
            int r = row0 + tid;
            if (r < M) {
                a1g[r * Hn + h] = sred[tid] + c1[h];
                a2g[r * Hn + h] = sred[128 + tid] + c2[h];
            }
        }
        __syncthreads();   // protect sred/smem before next tile
    }
}

// ---------------------------------------------------------------------------
// Edge-softmax + aggregation + ELU — single-pass ONLINE softmax.
// One warp per (node, head). HALFIN: gather fp16 ft.
// HALFSTORE: write fp16 output (feeds next GEMM); else fp32 out.
// ---------------------------------------------------------------------------
template<int VEC, bool HALFIN, bool HALFSTORE>
__global__ void aggregate_kernel(const void* __restrict__ ftv,
                                 const float* __restrict__ a1,
                                 const float* __restrict__ a2,
                                 const int* __restrict__ rowptr,
                                 const int* __restrict__ srcs,
                                 float* __restrict__ out,
                                 __half* __restrict__ outH,
                                 int Nn, int Hn, int ld) {
    constexpr int HIDo = VEC * 32;
    int gw   = (blockIdx.x * blockDim.x + threadIdx.x) >> 5;
    int lane = threadIdx.x & 31;
    if (gw >= Nn * Hn) return;
    int n = gw / Hn;
    int h = gw - n * Hn;
    int beg = rowptr[n];
    int end = rowptr[n + 1];
    float a1v = a1[n * Hn + h];

    float m = -1e30f, den = 0.f;
    float acc[VEC];
#pragma unroll
    for (int r = 0; r < VEC; r++) acc[r] = 0.f;

    for (int e0 = beg; e0 < end; e0 += 32) {
        int e = e0 + lane;
        float s = -1e30f;
        int sv = 0;
        if (e < end) {
            sv = srcs[e];
            float x = a1v + a2[sv * Hn + h];
            s = (x >= 0.f) ? x : 0.01f * x;
        }
        float bm = s;
        for (int o = 16; o; o >>= 1) bm = fmaxf(bm, __shfl_xor_sync(0xffffffffu, bm, o));
        float nm = fmaxf(m, bm);
        float scale = __expf(m - nm);
        den *= scale;
#pragma unroll
        for (int r = 0; r < VEC; r++) acc[r] *= scale;
        m = nm;

        float ev = __expf(s - nm);
        den += ev;

        int cnt = min(32, end - e0);
        for (int i = 0; i < cnt; i++) {
            float wi = __shfl_sync(0xffffffffu, ev, i);
            int   si = __shfl_sync(0xffffffffu, sv, i);
            if constexpr (HALFIN) {
                const __half* fp = (const __half*)ftv + (size_t)si * ld + h * HIDo;
                if (VEC == 4) {
                    uint2 raw = *((const uint2*)fp + lane);
                    float2 v01 = __half22float2(*reinterpret_cast<__half2*>(&raw.x));
                    float2 v23 = __half22float2(*reinterpret_cast<__half2*>(&raw.y));
                    acc[0] = fmaf(wi, v01.x, acc[0]);
                    acc[1] = fmaf(wi, v01.y, acc[1]);
                    acc[2] = fmaf(wi, v23.x, acc[2]);
                    acc[3] = fmaf(wi, v23.y, acc[3]);
                } else {
                    uint32_t raw = *((const uint32_t*)fp + lane);
                    float2 v01 = __half22float2(*reinterpret_cast<__half2*>(&raw));
                    acc[0] = fmaf(wi, v01.x, acc[0]);
                    acc[1] = fmaf(wi, v01.y, acc[1]);
                }
            } else {
                const float* fp = (const float*)ftv + (size_t)si * ld + h * HIDo;
                if (VEC == 4) {
                    float4 v = *((const float4*)fp + lane);
                    acc[0] = fmaf(wi, v.x, acc[0]);
                    acc[1] = fmaf(wi, v.y, acc[1]);
                    acc[2] = fmaf(wi, v.z, acc[2]);
                    acc[3] = fmaf(wi, v.w, acc[3]);
                } else {
                    float2 v = *((const float2*)fp + lane);
                    acc[0] = fmaf(wi, v.x, acc[0]);
                    acc[1] = fmaf(wi, v.y, acc[1]);
                }
            }
        }
    }
    for (int o = 16; o; o >>= 1) den += __shfl_xor_sync(0xffffffffu, den, o);
    float inv = 1.f / den;

    float r[VEC];
#pragma unroll
    for (int q = 0; q < VEC; q++) {
        float v = acc[q] * inv;
        r[q] = (v > 0.f) ? v : expm1f(v);
    }

    size_t ob = (size_t)n * ld + h * HIDo + lane * VEC;
    if constexpr (HALFSTORE) {
        if (VEC == 4) {
            *(__half2*)(outH + ob)     = __floats2half2_rn(r[0], r[1]);
            *(__half2*)(outH + ob + 2) = __floats2half2_rn(r[2], r[3]);
        } else {
            *(__half2*)(outH + ob) = __floats2half2_rn(r[0], r[1]);
        }
    } else {
        if (VEC == 4) {
            *(float4*)(out + ob) = make_float4(r[0], r[1], r[2], r[3]);
        } else {
            *(float2*)(out + ob) = make_float2(r[0], r[1]);
        }
    }
}

// ---------------------------------------------------------------------------
// Host launch
// ---------------------------------------------------------------------------
extern "C" void kernel_launch(void* const* d_in, const int* in_sizes, int n_in,
                              void* d_out, int out_size) {
    const float* features = (const float*)d_in[0];
    const int*   src      = (const int*)d_in[1];
    const int*   dst      = (const int*)d_in[2];
    const float* W0  = (const float*)d_in[3];
    const float* b0  = (const float*)d_in[4];
    const float* al0 = (const float*)d_in[5];
    const float* alb0= (const float*)d_in[6];
    const float* ar0 = (const float*)d_in[7];
    const float* arb0= (const float*)d_in[8];
    const float* W1  = (const float*)d_in[9];
    const float* b1  = (const float*)d_in[10];
    const float* al1 = (const float*)d_in[11];
    const float* alb1= (const float*)d_in[12];
    const float* ar1 = (const float*)d_in[13];
    const float* arb1= (const float*)d_in[14];
    const float* Wf  = (const float*)d_in[15];
    const float* bfv = (const float*)d_in[16];
    const float* alf = (const float*)d_in[17];
    const float* albf= (const float*)d_in[18];
    const float* arf = (const float*)d_in[19];
    const float* arbf= (const float*)d_in[20];

    float *ft, *a1, *a2, *c1, *c2;
    __half *Ah, *Bh;
    int *cnt, *rowptr, *cursor, *ssrc;
    cudaGetSymbolAddress((void**)&ft,  g_ft);
    cudaGetSymbolAddress((void**)&Ah,  g_Ah);
    cudaGetSymbolAddress((void**)&Bh,  g_Bh);
    cudaGetSymbolAddress((void**)&a1, g_a1);
    cudaGetSymbolAddress((void**)&a2, g_a2);
    cudaGetSymbolAddress((void**)&c1, g_c1);
    cudaGetSymbolAddress((void**)&c2, g_c2);
    cudaGetSymbolAddress((void**)&cnt, g_cnt);
    cudaGetSymbolAddress((void**)&rowptr, g_rowptr);
    cudaGetSymbolAddress((void**)&cursor, g_cursor);
    cudaGetSymbolAddress((void**)&ssrc, g_srcsorted);

    __half* fth = (__half*)ft;   // fp16 alias of the ft buffer (mid layers)

    // SMEM: 3 stages * (A(128*80) + B(BN*80)) + 1KB logit-reduction buffer
    constexpr int SMEM128 = 3 * (128 * 80 + 128 * 80) + 1024;  // 62464
    constexpr int SMEM64  = 3 * (128 * 80 + 64 * 80) + 1024;   // 47104
    cudaFuncSetAttribute(gemm_mma_kernel<128, true>,
                         cudaFuncAttributeMaxDynamicSharedMemorySize, SMEM128);
    cudaFuncSetAttribute(gemm_mma_kernel<64, false>,
                         cudaFuncAttributeMaxDynamicSharedMemorySize, SMEM64);

    // --- CSR build ---
    zero_int_kernel<<<(cN + 255) / 256, 256>>>(cnt, cN);
    hist_kernel<<<(cE + 255) / 256, 256>>>(dst, cnt, cE);
    scan_kernel<<<1, 1024>>>(cnt, rowptr, cursor, cN);
    scatter_kernel<<<(cE + 255) / 256, 256>>>(src, dst, cursor, ssrc, cE);

    const int gridM = (cN + 127) / 128;        // 157 row blocks
    const int nTilesMid = gridM * cH;          // 1256
    const int persistent = 296;                // 2 CTAs/SM * 148 SMs
    const int warpBlocksH = (cN * cH * 32 + 255) / 256;
    const int warpBlocks1 = (cN * 32 + 255) / 256;

    // --- logit constants for all 3 layers ---
    logit_const_kernel<<<1, 256>>>(b0, al0, alb0, ar0, arb0, c1, c2, cH, cHID);
    logit_const_kernel<<<1, 256>>>(b1, al1, alb1, ar1, arb1, c1 + cH, c2 + cH, cH, cHID);
    logit_const_kernel<<<1, 32>>>(bfv, alf, albf, arf, arbf, c1 + 2 * cH, c2 + 2 * cH, 1, cC);

    // --- layer 0 ---
    tohalf_kernel<<<(cN * cIN / 4 + 255) / 256, 256>>>(features, Ah, cN * cIN / 4);
    wprep_t_kernel<<<dim3(cIN / 32, cHID / 32, cH), dim3(32, 8)>>>(W0, Bh, cIN, cHID);
    gemm_mma_kernel<128, true><<<persistent, 256, SMEM128>>>(
        Ah, Bh, b0, al0, ar0, c1, c2, a1, a2, fth, cN, cIN, cHH, cH, nTilesMid);
    aggregate_kernel<4, true, true><<<warpBlocksH, 256>>>(
        fth, a1, a2, rowptr, ssrc, nullptr, Ah, cN, cH, cHH);

    // --- layer 1 ---
    wprep_t_kernel<<<dim3(cHH / 32, cHID / 32, cH), dim3(32, 8)>>>(W1, Bh, cHH, cHID);
    gemm_mma_kernel<128, true><<<persistent, 256, SMEM128>>>(
        Ah, Bh, b1, al1, ar1, c1 + cH, c2 + cH, a1, a2, fth, cN, cHH, cHH, cH, nTilesMid);
    aggregate_kernel<4, true, true><<<warpBlocksH, 256>>>(
        fth, a1, a2, rowptr, ssrc, nullptr, Ah, cN, cH, cHH);

    // --- final layer ---
    wprep_t_kernel<<<dim3(cHH / 32, cC / 32, 1), dim3(32, 8)>>>(Wf, Bh, cHH, cC);
    gemm_mma_kernel<64, false><<<gridM, 256, SMEM64>>>(
        Ah, Bh, bfv, alf, arf, c1 + 2 * cH, c2 + 2 * cH, a1, a2, ft,
        cN, cHH, cC, 1, gridM);
    aggregate_kernel<2, false, false><<<warpBlocks1, 256>>>(
        ft, a1, a2, rowptr, ssrc, (float*)d_out, nullptr, cN, 1, cC);
}